// round 12
// baseline (speedup 1.0000x reference)
#include <cuda_runtime.h>
#include <math.h>

#define NE   65536
#define DIM  512
#define DFF  2048
#define LN_EPS 1e-5f

typedef unsigned short u16;
typedef unsigned int   u32;
typedef signed char    s8;

// ---------------- scratch (device globals; no allocations) ----------------
__device__ __align__(16) float g_qs [(size_t)NE * DIM];
__device__ __align__(16) float g_ks [(size_t)NE * DIM];
__device__ __align__(16) float g_vs [(size_t)NE * DIM];
// int8 two-level activations
__device__ __align__(16) s8 g_aq1[(size_t)NE * DIM];   // ln_qry, later attn_output
__device__ __align__(16) s8 g_aq2[(size_t)NE * DIM];
__device__ __align__(16) s8 g_as1[(size_t)NE * DIM];   // ln_src, later y (ln2 out)
__device__ __align__(16) s8 g_as2[(size_t)NE * DIM];
__device__ __align__(16) s8 g_ff1[(size_t)NE * DFF];   // quantized gelu output
__device__ __align__(16) s8 g_ff2[(size_t)NE * DFF];
__device__ __align__(16) float g_ffF[(size_t)NE * DFF]; // fp32 gelu output (pre-quant)
// weights TRANSPOSED [n][k], two-level int8
#define OFF_Q 0
#define OFF_K (512*512)
#define OFF_V (2*512*512)
#define OFF_H (3*512*512)
#define OFF_1 (4*512*512)
#define OFF_2 (4*512*512 + 512*2048)
#define W_TOT (4*512*512 + 2*512*2048)
__device__ __align__(16) s8 g_wt1[W_TOT];
__device__ __align__(16) s8 g_wt2[W_TOT];
// scales
__device__ float g_saq[NE];
__device__ float g_sas[NE];
__device__ float g_sff[NE];
#define SC_Q 0
#define SC_K 512
#define SC_V 1024
#define SC_H 1536
#define SC_1 2048
#define SC_2 4096
__device__ float g_swc[4608];
// [0,DIM)=diag  [DIM,2DIM)=ksum  [2DIM]=|qs|^2  [2DIM+1]=|ks|^2
__device__ __align__(16) float g_red[2 * DIM + 8];

// ---------------- helpers ----------------
__device__ __forceinline__ u32 smem_u32(const void* p) {
    return (u32)__cvta_generic_to_shared(p);
}
__device__ __forceinline__ void ldsm_x4(u32* r, u32 a) {
    asm volatile("ldmatrix.sync.aligned.m8n8.x4.shared.b16 {%0,%1,%2,%3}, [%4];"
                 : "=r"(r[0]), "=r"(r[1]), "=r"(r[2]), "=r"(r[3]) : "r"(a));
}
__device__ __forceinline__ void imma16832(int* d, const u32* a, const u32* b) {
    asm volatile("mma.sync.aligned.m16n8k32.row.col.s32.s8.s8.s32 "
                 "{%0,%1,%2,%3}, {%4,%5,%6,%7}, {%8,%9}, {%0,%1,%2,%3};"
                 : "+r"(d[0]), "+r"(d[1]), "+r"(d[2]), "+r"(d[3])
                 : "r"(a[0]), "r"(a[1]), "r"(a[2]), "r"(a[3]), "r"(b[0]), "r"(b[1]));
}
__device__ __forceinline__ void cpa16(u32 dst, const void* src) {
    asm volatile("cp.async.cg.shared.global [%0], [%1], 16;" :: "r"(dst), "l"(src));
}
__device__ __forceinline__ void cp_commit() {
    asm volatile("cp.async.commit_group;");
}
template <int N>
__device__ __forceinline__ void cp_wait() {
    asm volatile("cp.async.wait_group %0;" :: "n"(N));
}
// quantize one value against inv-scale: q1 in [-127,127], q2 residual (x/s = q1 + q2/254)
__device__ __forceinline__ void quant1(float v, float inv, int& q1, int& q2) {
    float q = rintf(v * inv);
    q1 = (int)q;
    q2 = (int)rintf((v * inv - q) * 254.0f);
}
__device__ __forceinline__ u32 pack4b(int a, int b, int c, int d) {
    return (u32)(a & 0xFF) | ((u32)(b & 0xFF) << 8) | ((u32)(c & 0xFF) << 16) | ((u32)(d & 0xFF) << 24);
}

// ---------------- small kernels ----------------
__global__ void zero_red_kernel() {
    int i = blockIdx.x * blockDim.x + threadIdx.x;
    if (i < 2 * DIM + 8) g_red[i] = 0.0f;
}

// per-column max of W[K][N] -> g_swc[scoff + n] = colmax/127
__global__ void wcolmax_kernel(const float* __restrict__ src, int scoff, int K, int N) {
    int n = blockIdx.x * 256 + threadIdx.x;
    if (n >= N) return;
    float m = 0.0f;
    for (int k = 0; k < K; k++) m = fmaxf(m, fabsf(src[(size_t)k * N + n]));
    g_swc[scoff + n] = m * (1.0f / 127.0f) + 1e-30f;
}

// transpose + two-level quantize: W[K][N] -> Wt1/Wt2[N][K].  grid (N/32, K/32), block (32,8)
__global__ void wquant_t_kernel(const float* __restrict__ src, int woff, int scoff, int K, int N) {
    __shared__ float tile[32][33];
    int n0 = blockIdx.x * 32, k0 = blockIdx.y * 32;
    int tx = threadIdx.x, ty = threadIdx.y;
    #pragma unroll
    for (int i = 0; i < 4; i++)
        tile[ty + 8 * i][tx] = src[(size_t)(k0 + ty + 8 * i) * N + n0 + tx];
    __syncthreads();
    #pragma unroll
    for (int i = 0; i < 4; i++) {
        int nn = ty + 8 * i, kk = tx;
        float v = tile[kk][nn];
        float inv = 1.0f / g_swc[scoff + n0 + nn];
        int q1, q2; quant1(v, inv, q1, q2);
        size_t o = (size_t)woff + (size_t)(n0 + nn) * K + k0 + kk;
        g_wt1[o] = (s8)q1;
        g_wt2[o] = (s8)q2;
    }
}

// layernorm -> two-level int8 + row scale.  DST: 0 -> aq, 1 -> as
template <int DST>
__global__ void ln_q8(const float* __restrict__ x,
                      const float* __restrict__ gamma, const float* __restrict__ beta) {
    s8* B1 = (DST == 0) ? g_aq1 : g_as1;
    s8* B2 = (DST == 0) ? g_aq2 : g_as2;
    float* SC = (DST == 0) ? g_saq : g_sas;
    int row = blockIdx.x;
    int t = threadIdx.x;
    const float4* xin = (const float4*)(x + (size_t)row * DIM);
    float4 v = xin[t];
    float s1 = v.x + v.y + v.z + v.w;
    float s2 = v.x*v.x + v.y*v.y + v.z*v.z + v.w*v.w;
    #pragma unroll
    for (int o = 16; o; o >>= 1) {
        s1 += __shfl_xor_sync(0xffffffffu, s1, o);
        s2 += __shfl_xor_sync(0xffffffffu, s2, o);
    }
    __shared__ float sh1[4], sh2[4], shm[4];
    int w = t >> 5;
    if ((t & 31) == 0) { sh1[w] = s1; sh2[w] = s2; }
    __syncthreads();
    s1 = sh1[0] + sh1[1] + sh1[2] + sh1[3];
    s2 = sh2[0] + sh2[1] + sh2[2] + sh2[3];
    float mean = s1 * (1.0f / DIM);
    float var  = s2 * (1.0f / DIM) - mean * mean;
    float rstd = rsqrtf(var + LN_EPS);
    float4 gg = ((const float4*)gamma)[t];
    float4 bb = ((const float4*)beta)[t];
    float o0 = (v.x - mean) * rstd * gg.x + bb.x;
    float o1 = (v.y - mean) * rstd * gg.y + bb.y;
    float o2 = (v.z - mean) * rstd * gg.z + bb.z;
    float o3 = (v.w - mean) * rstd * gg.w + bb.w;
    float mx = fmaxf(fmaxf(fabsf(o0), fabsf(o1)), fmaxf(fabsf(o2), fabsf(o3)));
    #pragma unroll
    for (int o = 16; o; o >>= 1) mx = fmaxf(mx, __shfl_xor_sync(0xffffffffu, mx, o));
    if ((t & 31) == 0) shm[w] = mx;
    __syncthreads();
    mx = fmaxf(fmaxf(shm[0], shm[1]), fmaxf(shm[2], shm[3]));
    float s = mx * (1.0f / 127.0f) + 1e-30f;
    float inv = 1.0f / s;
    int a0,a1,a2,a3,b0,b1,b2,b3;
    quant1(o0, inv, a0, b0); quant1(o1, inv, a1, b1);
    quant1(o2, inv, a2, b2); quant1(o3, inv, a3, b3);
    ((u32*)(B1 + (size_t)row * DIM))[t] = pack4b(a0, a1, a2, a3);
    ((u32*)(B2 + (size_t)row * DIM))[t] = pack4b(b0, b1, b2, b3);
    if (t == 0) SC[row] = s;
}

// column reductions over qs/ks/vs
__global__ void reduce_kernel() {
    int c = blockIdx.x * 128 + threadIdx.x;
    int r0 = blockIdx.y * 256;
    float sd = 0.f, sk = 0.f, sk2 = 0.f, sq2 = 0.f;
    for (int r = 0; r < 256; r++) {
        size_t idx = (size_t)(r0 + r) * DIM + c;
        float kk = g_ks[idx], vv = g_vs[idx], qq = g_qs[idx];
        sd += kk * vv; sk += kk; sk2 += kk * kk; sq2 += qq * qq;
    }
    atomicAdd(&g_red[c], sd);
    atomicAdd(&g_red[DIM + c], sk);
    #pragma unroll
    for (int o = 16; o; o >>= 1) {
        sq2 += __shfl_xor_sync(0xffffffffu, sq2, o);
        sk2 += __shfl_xor_sync(0xffffffffu, sk2, o);
    }
    __shared__ float sa[4], sb[4];
    if ((threadIdx.x & 31) == 0) { sa[threadIdx.x >> 5] = sq2; sb[threadIdx.x >> 5] = sk2; }
    __syncthreads();
    if (threadIdx.x == 0) {
        atomicAdd(&g_red[2 * DIM],     sa[0] + sa[1] + sa[2] + sa[3]);
        atomicAdd(&g_red[2 * DIM + 1], sb[0] + sb[1] + sb[2] + sb[3]);
    }
}

// attention finalize -> two-level int8 into g_aq1/2 + g_saq
__global__ void attn_q8() {
    int row = blockIdx.x;
    int t = threadIdx.x;  // cols 4t..4t+3; head = t/16
    float rFq = rsqrtf(g_red[2 * DIM]);
    float rFk = rsqrtf(g_red[2 * DIM + 1]);
    const float nf = (float)NE;
    size_t base = (size_t)row * DIM;
    float4 q  = ((const float4*)(g_qs + base))[t];
    float4 v  = ((const float4*)(g_vs + base))[t];
    float4 dg = ((const float4*)(g_red))[t];
    float4 km = ((const float4*)(g_red + DIM))[t];
    float p = (q.x*km.x + q.y*km.y + q.z*km.z + q.w*km.w) * (rFq * rFk);
    #pragma unroll
    for (int o = 8; o; o >>= 1) p += __shfl_xor_sync(0xffffffffu, p, o);
    float inv0 = 1.0f / (p + nf);
    float s = rFq * rFk;
    float o0 = (q.x * s * dg.x + v.x * nf) * inv0;
    float o1 = (q.y * s * dg.y + v.y * nf) * inv0;
    float o2 = (q.z * s * dg.z + v.z * nf) * inv0;
    float o3 = (q.w * s * dg.w + v.w * nf) * inv0;
    float mx = fmaxf(fmaxf(fabsf(o0), fabsf(o1)), fmaxf(fabsf(o2), fabsf(o3)));
    #pragma unroll
    for (int o = 16; o; o >>= 1) mx = fmaxf(mx, __shfl_xor_sync(0xffffffffu, mx, o));
    __shared__ float shm[4];
    if ((t & 31) == 0) shm[t >> 5] = mx;
    __syncthreads();
    mx = fmaxf(fmaxf(shm[0], shm[1]), fmaxf(shm[2], shm[3]));
    float sc = mx * (1.0f / 127.0f) + 1e-30f;
    float inv = 1.0f / sc;
    int a0,a1,a2,a3,b0,b1,b2,b3;
    quant1(o0, inv, a0, b0); quant1(o1, inv, a1, b1);
    quant1(o2, inv, a2, b2); quant1(o3, inv, a3, b3);
    ((u32*)(g_aq1 + base))[t] = pack4b(a0, a1, a2, a3);
    ((u32*)(g_aq2 + base))[t] = pack4b(b0, b1, b2, b3);
    if (t == 0) g_saq[row] = sc;
}

// quantize gelu rows: g_ffF[NE][DFF] -> g_ff1/2 + g_sff.  block 256, 1 row/block
__global__ void qrow_ff() {
    int row = blockIdx.x;
    int t = threadIdx.x;
    size_t base = (size_t)row * DFF;
    float4 v0 = ((const float4*)(g_ffF + base))[t * 2];
    float4 v1 = ((const float4*)(g_ffF + base))[t * 2 + 1];
    float mx = fmaxf(fmaxf(fabsf(v0.x), fabsf(v0.y)), fmaxf(fabsf(v0.z), fabsf(v0.w)));
    mx = fmaxf(mx, fmaxf(fmaxf(fabsf(v1.x), fabsf(v1.y)), fmaxf(fabsf(v1.z), fabsf(v1.w))));
    #pragma unroll
    for (int o = 16; o; o >>= 1) mx = fmaxf(mx, __shfl_xor_sync(0xffffffffu, mx, o));
    __shared__ float shm[8];
    if ((t & 31) == 0) shm[t >> 5] = mx;
    __syncthreads();
    mx = shm[0];
    #pragma unroll
    for (int i = 1; i < 8; i++) mx = fmaxf(mx, shm[i]);
    float sc = mx * (1.0f / 127.0f) + 1e-30f;
    float inv = 1.0f / sc;
    int a0,a1,a2,a3,b0,b1,b2,b3;
    quant1(v0.x, inv, a0, b0); quant1(v0.y, inv, a1, b1);
    quant1(v0.z, inv, a2, b2); quant1(v0.w, inv, a3, b3);
    ((u32*)(g_ff1 + base))[t * 2] = pack4b(a0, a1, a2, a3);
    ((u32*)(g_ff2 + base))[t * 2] = pack4b(b0, b1, b2, b3);
    quant1(v1.x, inv, a0, b0); quant1(v1.y, inv, a1, b1);
    quant1(v1.z, inv, a2, b2); quant1(v1.w, inv, a3, b3);
    ((u32*)(g_ff1 + base))[t * 2 + 1] = pack4b(a0, a1, a2, a3);
    ((u32*)(g_ff2 + base))[t * 2 + 1] = pack4b(b0, b1, b2, b3);
    if (t == 0) g_sff[row] = sc;
}

// ---------------- two-level int8 tensor-core GEMM ----------------
// A = sA(a1 + a2/254), B = sB(b1 + b2/254); C = sA·sB·(acc1 + acc2/254),
//   acc1 = a1@b1, acc2 = a1@b2 + a2@b1 (a2b2/254^2 dropped, ~6e-5 rel).
// Weights in [n][k] layout; A and B tiles share layout (rows of 64B, swizzle c^(r&3)).
// CTA 128x128, 8 warps 32x64, k-slab 64, 3-stage cp.async, 1 sync/slab.
// ASEL: 0 g_aq, 1 g_as, 2 g_ff     CSEL: 0 qs, 1 ks, 2 vs, 3 Carg, 4 g_ffF
// EPI 0: +bias  1: +bias+res  2: gelu(+bias)  3: +bias+res (res==Carg ok)
// Stage (bytes): A1@0 (8K), A2@8192, B1@16384, B2@24576.  32KB/stage.
#define STG_BYTES 32768
#define SMEM_DYN (3 * STG_BYTES)
template <int EPI, int ASEL, int CSEL>
__global__ void __launch_bounds__(256)
mma_gemm(int boff, int scoff, const float* __restrict__ bias, const float* __restrict__ res,
         float* __restrict__ Carg, int M, int N, int K)
{
    const s8* A1 = (ASEL == 0) ? g_aq1 : (ASEL == 1) ? g_as1 : g_ff1;
    const s8* A2 = (ASEL == 0) ? g_aq2 : (ASEL == 1) ? g_as2 : g_ff2;
    const float* sAarr = (ASEL == 0) ? g_saq : (ASEL == 1) ? g_sas : g_sff;
    const s8* B1 = g_wt1 + boff;
    const s8* B2 = g_wt2 + boff;
    const float* sBarr = g_swc + scoff;
    float* C = (CSEL == 0) ? g_qs : (CSEL == 1) ? g_ks : (CSEL == 2) ? g_vs :
               (CSEL == 4) ? g_ffF : Carg;

    extern __shared__ __align__(16) s8 smem[];
    const int tid = threadIdx.x, lane = tid & 31, warp = tid >> 5;
    const int wm = warp >> 1, wn = warp & 1;            // 4 x 2 warp grid, 32x64
    const int row0 = blockIdx.y * 128;
    const int col0 = blockIdx.x * 128;

    int acc1[2][8][4], acc2[2][8][4];
    #pragma unroll
    for (int i = 0; i < 2; i++)
        #pragma unroll
        for (int j = 0; j < 8; j++)
            #pragma unroll
            for (int c = 0; c < 4; c++) { acc1[i][j][c] = 0; acc2[i][j][c] = 0; }

    const u32 sBase = smem_u32(smem);

    // ldsm lane mappings (byte-identical to bf16 k16 case)
    const int lrA = lane & 15, lgA = lane >> 4;
    const int lrB = (lane & 7) + ((lane >> 4) << 3);
    const int kcB = (lane >> 3) & 1;
    // fill mapping: 256 threads cover 128 rows x 4 chunks(16B) per tile, 2 row-halves
    const int ar = tid >> 2, aq = tid & 3;
    const u32 dA0 = (u32)(ar * 64 + 16 * (aq ^ (ar & 3)));

    const int nk = K >> 6;  // K/64 slabs (8 or 32)

    auto load_stage = [&](int stage, int slab) {
        int k0 = slab << 6;
        u32 sb = sBase + stage * STG_BYTES;
        const s8* pa0 = A1 + (size_t)(row0 + ar) * K + k0 + aq * 16;
        const s8* pa1 = A1 + (size_t)(row0 + ar + 64) * K + k0 + aq * 16;
        const s8* pa2 = A2 + (size_t)(row0 + ar) * K + k0 + aq * 16;
        const s8* pa3 = A2 + (size_t)(row0 + ar + 64) * K + k0 + aq * 16;
        cpa16(sb + dA0, pa0);
        cpa16(sb + dA0 + 4096, pa1);
        cpa16(sb + 8192 + dA0, pa2);
        cpa16(sb + 8192 + dA0 + 4096, pa3);
        const s8* pb0 = B1 + (size_t)(col0 + ar) * K + k0 + aq * 16;
        const s8* pb1 = B1 + (size_t)(col0 + ar + 64) * K + k0 + aq * 16;
        const s8* pb2 = B2 + (size_t)(col0 + ar) * K + k0 + aq * 16;
        const s8* pb3 = B2 + (size_t)(col0 + ar + 64) * K + k0 + aq * 16;
        cpa16(sb + 16384 + dA0, pb0);
        cpa16(sb + 16384 + dA0 + 4096, pb1);
        cpa16(sb + 24576 + dA0, pb2);
        cpa16(sb + 24576 + dA0 + 4096, pb3);
        cp_commit();
    };

    load_stage(0, 0);
    load_stage(1, 1);

    int stage = 0;
    for (int it = 0; it < nk; it++) {
        if (it + 1 < nk) cp_wait<1>(); else cp_wait<0>();
        __syncthreads();   // single barrier per slab

        const u32 stA = sBase + stage * STG_BYTES;
        #pragma unroll
        for (int ks = 0; ks < 64; ks += 32) {
            const int c0 = ks >> 4;     // 16B-chunk index: 0 or 2
            u32 a1f[2][4], a2f[2][4];
            #pragma unroll
            for (int i = 0; i < 2; i++) {
                int r = wm * 32 + i * 16 + lrA;
                u32 off = (u32)(r * 64 + 16 * ((c0 + lgA) ^ (r & 3)));
                ldsm_x4(a1f[i], stA + off);
                ldsm_x4(a2f[i], stA + 8192 + off);
            }
            #pragma unroll
            for (int jp = 0; jp < 4; jp++) {
                int r = wn * 64 + jp * 16 + lrB;
                u32 off = 16384 + (u32)(r * 64 + 16 * ((c0 + kcB) ^ (r & 3)));
                u32 b1f[4], b2f[4];
                ldsm_x4(b1f, stA + off);
                ldsm_x4(b2f, stA + off + 8192);
                #pragma unroll
                for (int i = 0; i < 2; i++) {
                    #pragma unroll
                    for (int jj = 0; jj < 2; jj++) {
                        imma16832(acc1[i][jp * 2 + jj], a1f[i], b1f + 2 * jj);
                        imma16832(acc2[i][jp * 2 + jj], a1f[i], b2f + 2 * jj);
                        imma16832(acc2[i][jp * 2 + jj], a2f[i], b1f + 2 * jj);
                    }
                }
            }
        }
        if (it + 2 < nk) {
            int ns = stage + 2;
            if (ns >= 3) ns -= 3;
            load_stage(ns, it + 2);
        }
        stage = (stage == 2) ? 0 : stage + 1;
    }

    // epilogue: dequant + bias (+res/gelu)
    const int cg = lane >> 2, ct = lane & 3;
    float sa[2][2];
    #pragma unroll
    for (int i = 0; i < 2; i++)
        #pragma unroll
        for (int h = 0; h < 2; h++)
            sa[i][h] = sAarr[row0 + wm * 32 + i * 16 + cg + h * 8];
    #pragma unroll
    for (int i = 0; i < 2; i++) {
        #pragma unroll
        for (int jn = 0; jn < 8; jn++) {
            int col = col0 + wn * 64 + jn * 8 + ct * 2;
            float bb0 = bias[col], bb1 = bias[col + 1];
            float sb0 = sBarr[col], sb1 = sBarr[col + 1];
            #pragma unroll
            for (int h = 0; h < 2; h++) {
                int row = row0 + wm * 32 + i * 16 + cg + h * 8;
                size_t idx = (size_t)row * N + col;
                float ss = sa[i][h];
                float v0 = ((float)acc1[i][jn][h * 2 + 0]
                            + (float)acc2[i][jn][h * 2 + 0] * (1.0f / 254.0f)) * (ss * sb0) + bb0;
                float v1 = ((float)acc1[i][jn][h * 2 + 1]
                            + (float)acc2[i][jn][h * 2 + 1] * (1.0f / 254.0f)) * (ss * sb1) + bb1;
                if (EPI == 1 || EPI == 3) {
                    float2 r2 = *(const float2*)(res + idx);
                    v0 += r2.x; v1 += r2.y;
                }
                if (EPI == 2) {
                    v0 = 0.5f * v0 * (1.0f + erff(v0 * 0.7071067811865476f));
                    v1 = 0.5f * v1 * (1.0f + erff(v1 * 0.7071067811865476f));
                }
                *(float2*)(C + idx) = make_float2(v0, v1);
            }
        }
    }
}

// ---------------- launcher ----------------
extern "C" void kernel_launch(void* const* d_in, const int* in_sizes, int n_in,
                              void* d_out_v, int out_size) {
    const float* q_in = (const float*)d_in[0];
    const float* s_in = (const float*)d_in[1];
    const float* Wq = (const float*)d_in[2];  const float* bq = (const float*)d_in[3];
    const float* Wk = (const float*)d_in[4];  const float* bk = (const float*)d_in[5];
    const float* Wv = (const float*)d_in[6];  const float* bv = (const float*)d_in[7];
    const float* Wh = (const float*)d_in[8];  const float* bh = (const float*)d_in[9];
    const float* lnkg = (const float*)d_in[10]; const float* lnkb = (const float*)d_in[11];
    const float* lnqg = (const float*)d_in[12]; const float* lnqb = (const float*)d_in[13];
    const float* ln2g = (const float*)d_in[14]; const float* ln2b = (const float*)d_in[15];
    const float* W1 = (const float*)d_in[16]; const float* b1 = (const float*)d_in[17];
    const float* W2 = (const float*)d_in[18]; const float* b2 = (const float*)d_in[19];
    float* out = (float*)d_out_v;

    cudaFuncSetAttribute(mma_gemm<0,0,0>, cudaFuncAttributeMaxDynamicSharedMemorySize, SMEM_DYN);
    cudaFuncSetAttribute(mma_gemm<0,1,1>, cudaFuncAttributeMaxDynamicSharedMemorySize, SMEM_DYN);
    cudaFuncSetAttribute(mma_gemm<0,1,2>, cudaFuncAttributeMaxDynamicSharedMemorySize, SMEM_DYN);
    cudaFuncSetAttribute(mma_gemm<1,0,3>, cudaFuncAttributeMaxDynamicSharedMemorySize, SMEM_DYN);
    cudaFuncSetAttribute(mma_gemm<2,1,4>, cudaFuncAttributeMaxDynamicSharedMemorySize, SMEM_DYN);
    cudaFuncSetAttribute(mma_gemm<3,2,3>, cudaFuncAttributeMaxDynamicSharedMemorySize, SMEM_DYN);

    dim3 blk(256);
    dim3 gD(DIM / 128, NE / 128);      // (4, 512)
    dim3 tb(32, 8);

    // weight quantization (transposed, two-level)
    wcolmax_kernel<<<2, 256>>>(Wq, SC_Q, 512, 512);
    wquant_t_kernel<<<dim3(16, 16), tb>>>(Wq, OFF_Q, SC_Q, 512, 512);
    wcolmax_kernel<<<2, 256>>>(Wk, SC_K, 512, 512);
    wquant_t_kernel<<<dim3(16, 16), tb>>>(Wk, OFF_K, SC_K, 512, 512);
    wcolmax_kernel<<<2, 256>>>(Wv, SC_V, 512, 512);
    wquant_t_kernel<<<dim3(16, 16), tb>>>(Wv, OFF_V, SC_V, 512, 512);
    wcolmax_kernel<<<2, 256>>>(Wh, SC_H, 512, 512);
    wquant_t_kernel<<<dim3(16, 16), tb>>>(Wh, OFF_H, SC_H, 512, 512);
    wcolmax_kernel<<<8, 256>>>(W1, SC_1, 512, 2048);
    wquant_t_kernel<<<dim3(64, 16), tb>>>(W1, OFF_1, SC_1, 512, 2048);
    wcolmax_kernel<<<2, 256>>>(W2, SC_2, 2048, 512);
    wquant_t_kernel<<<dim3(16, 64), tb>>>(W2, OFF_2, SC_2, 2048, 512);

    ln_q8<0><<<NE, 128>>>(q_in, lnqg, lnqb);   // ln_qry -> aq
    ln_q8<1><<<NE, 128>>>(s_in, lnkg, lnkb);   // ln_src -> as
    zero_red_kernel<<<(2 * DIM + 8 + 127) / 128, 128>>>();

    mma_gemm<0, 0, 0><<<gD, blk, SMEM_DYN>>>(OFF_Q, SC_Q, bq, nullptr, nullptr, NE, DIM, DIM);  // qs
    mma_gemm<0, 1, 1><<<gD, blk, SMEM_DYN>>>(OFF_K, SC_K, bk, nullptr, nullptr, NE, DIM, DIM);  // ks
    mma_gemm<0, 1, 2><<<gD, blk, SMEM_DYN>>>(OFF_V, SC_V, bv, nullptr, nullptr, NE, DIM, DIM);  // vs

    reduce_kernel<<<dim3(DIM / 128, 256), 128>>>();
    attn_q8<<<NE, 128>>>();                    // -> aq (quantized attn_output)

    // h_pre_ffn = source + attn @ Wh + bh -> out
    mma_gemm<1, 0, 3><<<gD, blk, SMEM_DYN>>>(OFF_H, SC_H, bh, s_in, out, NE, DIM, DIM);
    // y = LN(out) -> as
    ln_q8<1><<<NE, 128>>>(out, ln2g, ln2b);
    // gelu(y @ W1 + b1) -> g_ffF (fp32)
    mma_gemm<2, 1, 4><<<dim3(DFF / 128, NE / 128), blk, SMEM_DYN>>>(OFF_1, SC_1, b1, nullptr, nullptr, NE, DFF, DIM);
    // quantize gelu rows
    qrow_ff<<<NE, 256>>>();
    // out = out + ffn @ W2 + b2
    mma_gemm<3, 2, 3><<<gD, blk, SMEM_DYN>>>(OFF_2, SC_2, b2, out, out, NE, DIM, DFF);
}

// round 13
// speedup vs baseline: 3.9633x; 3.9633x over previous
#include <cuda_runtime.h>
#include <math.h>

#define NE   65536
#define DIM  512
#define DFF  2048
#define LN_EPS 1e-5f

typedef unsigned short u16;
typedef unsigned int   u32;

// ---------------- scratch (device globals; no allocations) ----------------
__device__ __align__(16) float g_qs [(size_t)NE * DIM];
__device__ __align__(16) float g_ks [(size_t)NE * DIM];
__device__ __align__(16) float g_vs [(size_t)NE * DIM];
// single-fp16 activations
__device__ __align__(16) u16 g_aq[(size_t)NE * DIM];   // ln_qry, later attn_output
__device__ __align__(16) u16 g_as[(size_t)NE * DIM];   // ln_src, later y (ln2 out)
__device__ __align__(16) u16 g_ff[(size_t)NE * DFF];   // gelu output
// weights split fp16 hi/lo (B side exact to ~2^-22)
#define OFF_Q 0
#define OFF_K (512*512)
#define OFF_V (2*512*512)
#define OFF_H (3*512*512)
#define OFF_1 (4*512*512)
#define OFF_2 (4*512*512 + 512*2048)
#define W_TOT (4*512*512 + 2*512*2048)
__device__ __align__(16) u16 g_w_h[W_TOT];
__device__ __align__(16) u16 g_w_l[W_TOT];
// [0,DIM)=diag  [DIM,2DIM)=ksum  [2DIM]=|qs|^2  [2DIM+1]=|ks|^2
__device__ __align__(16) float g_red[2 * DIM + 8];

// ---------------- fp16-as-bits helpers ----------------
__device__ __forceinline__ u16 f2h(float x) {
    u16 h;
    asm("cvt.rn.f16.f32 %0, %1;" : "=h"(h) : "f"(x));
    return h;
}
__device__ __forceinline__ float h2f(u16 h) {
    float f;
    asm("cvt.f32.f16 %0, %1;" : "=f"(f) : "h"(h));
    return f;
}
__device__ __forceinline__ void splitw(float x, u16& h, u16& l) {
    h = f2h(x);
    l = f2h(x - h2f(h));
}
__device__ __forceinline__ u32 pack2(u16 a, u16 b) {
    return (u32)a | ((u32)b << 16);
}

__device__ __forceinline__ u32 smem_u32(const void* p) {
    return (u32)__cvta_generic_to_shared(p);
}
__device__ __forceinline__ void ldsm_x4(u32* r, u32 a) {
    asm volatile("ldmatrix.sync.aligned.m8n8.x4.shared.b16 {%0,%1,%2,%3}, [%4];"
                 : "=r"(r[0]), "=r"(r[1]), "=r"(r[2]), "=r"(r[3]) : "r"(a));
}
__device__ __forceinline__ void ldsm_x4t(u32* r, u32 a) {
    asm volatile("ldmatrix.sync.aligned.m8n8.x4.trans.shared.b16 {%0,%1,%2,%3}, [%4];"
                 : "=r"(r[0]), "=r"(r[1]), "=r"(r[2]), "=r"(r[3]) : "r"(a));
}
__device__ __forceinline__ void mma16816(float* d, const u32* a, const u32* b) {
    asm volatile("mma.sync.aligned.m16n8k16.row.col.f32.f16.f16.f32 "
                 "{%0,%1,%2,%3}, {%4,%5,%6,%7}, {%8,%9}, {%0,%1,%2,%3};"
                 : "+f"(d[0]), "+f"(d[1]), "+f"(d[2]), "+f"(d[3])
                 : "r"(a[0]), "r"(a[1]), "r"(a[2]), "r"(a[3]), "r"(b[0]), "r"(b[1]));
}
__device__ __forceinline__ void cpa16(u32 dst, const void* src) {
    asm volatile("cp.async.cg.shared.global [%0], [%1], 16;" :: "r"(dst), "l"(src));
}
__device__ __forceinline__ void cp_commit() {
    asm volatile("cp.async.commit_group;");
}
template <int N>
__device__ __forceinline__ void cp_wait() {
    asm volatile("cp.async.wait_group %0;" :: "n"(N));
}

// ---------------- small kernels ----------------
__global__ void zero_red_kernel() {
    int i = blockIdx.x * blockDim.x + threadIdx.x;
    if (i < 2 * DIM + 8) g_red[i] = 0.0f;
}

__global__ void wsplit_kernel(const float* __restrict__ src, int off, int n4) {
    int i = blockIdx.x * 256 + threadIdx.x;
    if (i < n4) {
        float4 v = ((const float4*)src)[i];
        u16 h0,h1,h2,h3,l0,l1,l2,l3;
        splitw(v.x,h0,l0); splitw(v.y,h1,l1); splitw(v.z,h2,l2); splitw(v.w,h3,l3);
        size_t o = (size_t)off + (size_t)i * 4;
        *(u32*)(g_w_h + o)     = pack2(h0, h1);
        *(u32*)(g_w_h + o + 2) = pack2(h2, h3);
        *(u32*)(g_w_l + o)     = pack2(l0, l1);
        *(u32*)(g_w_l + o + 2) = pack2(l2, l3);
    }
}

// layernorm -> single fp16.  DST: 0 -> g_aq, 1 -> g_as
template <int DST>
__global__ void ln_kernel(const float* __restrict__ x,
                          const float* __restrict__ gamma, const float* __restrict__ beta) {
    u16* y = (DST == 0) ? g_aq : g_as;
    int row = blockIdx.x;
    int t = threadIdx.x;
    const float4* xin = (const float4*)(x + (size_t)row * DIM);
    float4 v = xin[t];
    float s1 = v.x + v.y + v.z + v.w;
    float s2 = v.x*v.x + v.y*v.y + v.z*v.z + v.w*v.w;
    #pragma unroll
    for (int o = 16; o; o >>= 1) {
        s1 += __shfl_xor_sync(0xffffffffu, s1, o);
        s2 += __shfl_xor_sync(0xffffffffu, s2, o);
    }
    __shared__ float sh1[4], sh2[4];
    int w = t >> 5;
    if ((t & 31) == 0) { sh1[w] = s1; sh2[w] = s2; }
    __syncthreads();
    s1 = sh1[0] + sh1[1] + sh1[2] + sh1[3];
    s2 = sh2[0] + sh2[1] + sh2[2] + sh2[3];
    float mean = s1 * (1.0f / DIM);
    float var  = s2 * (1.0f / DIM) - mean * mean;
    float rstd = rsqrtf(var + LN_EPS);
    float4 gg = ((const float4*)gamma)[t];
    float4 bb = ((const float4*)beta)[t];
    float o0 = (v.x - mean) * rstd * gg.x + bb.x;
    float o1 = (v.y - mean) * rstd * gg.y + bb.y;
    float o2 = (v.z - mean) * rstd * gg.z + bb.z;
    float o3 = (v.w - mean) * rstd * gg.w + bb.w;
    size_t off = (size_t)row * DIM + t * 4;
    *(u32*)(y + off)     = pack2(f2h(o0), f2h(o1));
    *(u32*)(y + off + 2) = pack2(f2h(o2), f2h(o3));
}

// column reductions over qs/ks/vs
__global__ void reduce_kernel() {
    int c = blockIdx.x * 128 + threadIdx.x;
    int r0 = blockIdx.y * 256;
    float sd = 0.f, sk = 0.f, sk2 = 0.f, sq2 = 0.f;
    for (int r = 0; r < 256; r++) {
        size_t idx = (size_t)(r0 + r) * DIM + c;
        float kk = g_ks[idx], vv = g_vs[idx], qq = g_qs[idx];
        sd += kk * vv; sk += kk; sk2 += kk * kk; sq2 += qq * qq;
    }
    atomicAdd(&g_red[c], sd);
    atomicAdd(&g_red[DIM + c], sk);
    #pragma unroll
    for (int o = 16; o; o >>= 1) {
        sq2 += __shfl_xor_sync(0xffffffffu, sq2, o);
        sk2 += __shfl_xor_sync(0xffffffffu, sk2, o);
    }
    __shared__ float sa[4], sb[4];
    if ((threadIdx.x & 31) == 0) { sa[threadIdx.x >> 5] = sq2; sb[threadIdx.x >> 5] = sk2; }
    __syncthreads();
    if (threadIdx.x == 0) {
        atomicAdd(&g_red[2 * DIM],     sa[0] + sa[1] + sa[2] + sa[3]);
        atomicAdd(&g_red[2 * DIM + 1], sb[0] + sb[1] + sb[2] + sb[3]);
    }
}

// attention finalize -> single fp16 into g_aq
__global__ void attn_kernel() {
    int row = blockIdx.x;
    int t = threadIdx.x;  // cols 4t..4t+3; head = t/16
    float rFq = rsqrtf(g_red[2 * DIM]);
    float rFk = rsqrtf(g_red[2 * DIM + 1]);
    const float nf = (float)NE;
    size_t base = (size_t)row * DIM;
    float4 q  = ((const float4*)(g_qs + base))[t];
    float4 v  = ((const float4*)(g_vs + base))[t];
    float4 dg = ((const float4*)(g_red))[t];
    float4 km = ((const float4*)(g_red + DIM))[t];
    float p = (q.x*km.x + q.y*km.y + q.z*km.z + q.w*km.w) * (rFq * rFk);
    #pragma unroll
    for (int o = 8; o; o >>= 1) p += __shfl_xor_sync(0xffffffffu, p, o);
    float inv = 1.0f / (p + nf);
    float s = rFq * rFk;
    float o0 = (q.x * s * dg.x + v.x * nf) * inv;
    float o1 = (q.y * s * dg.y + v.y * nf) * inv;
    float o2 = (q.z * s * dg.z + v.z * nf) * inv;
    float o3 = (q.w * s * dg.w + v.w * nf) * inv;
    size_t off = base + t * 4;
    *(u32*)(g_aq + off)     = pack2(f2h(o0), f2h(o1));
    *(u32*)(g_aq + off + 2) = pack2(f2h(o2), f2h(o3));
}

// ---------------- fp16 2-term tensor-core GEMM, 3-stage cp.async, 1 sync/slab ----------------
// C = A@(Bh+Bl): A single fp16 (error ~2.8e-4), weights exact to ~2^-22.
// ASEL: 0 -> g_aq, 1 -> g_as, 2 -> g_ff     CSEL: 0 qs, 1 ks, 2 vs, 3 Carg, 4 g_ff(fp16)
// EPI 0: +bias   EPI 1: +bias+res   EPI 2: gelu(+bias)   EPI 3: +bias+res (res==Carg ok)
// Stage (bytes): A[128x32]@0 (8K), B_h[32x128]@8192 (8K), B_l@16384 (8K).  24KB/stage.
#define STG_BYTES 24576
#define SMEM_DYN (3 * STG_BYTES)
template <int EPI, int ASEL, int CSEL>
__global__ void __launch_bounds__(256)
mma_gemm(int boff, const float* __restrict__ bias, const float* __restrict__ res,
         float* __restrict__ Carg, int M, int N, int K)
{
    const u16* A  = (ASEL == 0) ? g_aq : (ASEL == 1) ? g_as : g_ff;
    const u16* Bh = g_w_h + boff;
    const u16* Bl = g_w_l + boff;
    float* C = (CSEL == 0) ? g_qs : (CSEL == 1) ? g_ks : (CSEL == 2) ? g_vs : Carg;

    extern __shared__ __align__(16) u16 smem[];
    const int tid = threadIdx.x, lane = tid & 31, warp = tid >> 5;
    const int wm = warp >> 1, wn = warp & 1;            // 4 x 2 warp grid, 32x64
    const int row0 = blockIdx.y * 128;
    const int col0 = blockIdx.x * 128;

    float acc[2][8][4];
    #pragma unroll
    for (int i = 0; i < 2; i++)
        #pragma unroll
        for (int j = 0; j < 8; j++)
            #pragma unroll
            for (int c = 0; c < 4; c++) acc[i][j][c] = 0.0f;

    const u32 sBase = smem_u32(smem);

    const int lrA = lane & 15, lgA = lane >> 4;
    const int lkB = (lane & 7) + ((lane >> 3) & 1) * 8;
    const int lgB = lane >> 4;
    const int ar = tid >> 2, aq = tid & 3;
    const int br = tid >> 4, bq = tid & 15;

    // per-thread smem dst offsets (bytes, relative to stage base)
    u32 dA0 = (u32)((ar)      * 32 + 8 * (aq ^ (((ar)      >> 1) & 3))) * 2;
    u32 dA1 = (u32)((ar + 64) * 32 + 8 * (aq ^ (((ar + 64) >> 1) & 3))) * 2;
    u32 dB0 = (u32)((br)      * 128 + 8 * (bq ^ ((br)      & 7))) * 2 + 8192;
    u32 dB1 = (u32)((br + 16) * 128 + 8 * (bq ^ ((br + 16) & 7))) * 2 + 8192;

    const int nk = K >> 5;  // K/32 slabs (16 or 64)

    auto load_stage = [&](int stage, int slab) {
        int k0 = slab << 5;
        u32 sb = sBase + stage * STG_BYTES;
        const u16* a0 = A + (size_t)(row0 + ar) * K + k0 + aq * 8;
        const u16* a1 = A + (size_t)(row0 + ar + 64) * K + k0 + aq * 8;
        cpa16(sb + dA0, a0);
        cpa16(sb + dA1, a1);
        const u16* b0  = Bh + (size_t)(k0 + br) * N + col0 + bq * 8;
        const u16* b1  = Bh + (size_t)(k0 + br + 16) * N + col0 + bq * 8;
        const u16* b0l = Bl + (size_t)(k0 + br) * N + col0 + bq * 8;
        const u16* b1l = Bl + (size_t)(k0 + br + 16) * N + col0 + bq * 8;
        cpa16(sb + dB0, b0);
        cpa16(sb + dB1, b1);
        cpa16(sb + dB0 + 8192, b0l);
        cpa16(sb + dB1 + 8192, b1l);
        cp_commit();
    };

    // prologue: 2 stages in flight
    load_stage(0, 0);
    load_stage(1, 1);

    int stage = 0;
    for (int it = 0; it < nk; it++) {
        if (it + 1 < nk) cp_wait<1>(); else cp_wait<0>();
        __syncthreads();   // single barrier per slab

        const u32 stA = sBase + stage * STG_BYTES;
        const u32 stB = stA + 8192;
        #pragma unroll
        for (int ks = 0; ks < 32; ks += 16) {
            u32 ahf[2][4];
            #pragma unroll
            for (int i = 0; i < 2; i++) {
                int r = wm * 32 + i * 16 + lrA;
                int G = (ks >> 3) + lgA;
                u32 off = (u32)(r * 32 + 8 * (G ^ ((r >> 1) & 3))) * 2;
                ldsm_x4(ahf[i], stA + off);
            }
            int kB = ks + lkB;
            int swb = kB & 7;
            #pragma unroll
            for (int jp = 0; jp < 4; jp++) {
                int G = wn * 8 + jp * 2 + lgB;
                u32 off = (u32)(kB * 128 + 8 * (G ^ swb)) * 2;
                u32 bhf[4], blf[4];
                ldsm_x4t(bhf, stB + off);
                ldsm_x4t(blf, stB + 8192 + off);
                #pragma unroll
                for (int i = 0; i < 2; i++) {
                    #pragma unroll
                    for (int jj = 0; jj < 2; jj++) {
                        float* d = acc[i][jp * 2 + jj];
                        mma16816(d, ahf[i], bhf + 2 * jj);
                        mma16816(d, ahf[i], blf + 2 * jj);
                    }
                }
            }
        }
        // refill the stage consumed 2 iterations ago; no trailing barrier needed.
        if (it + 2 < nk) {
            int ns = stage + 2;
            if (ns >= 3) ns -= 3;
            load_stage(ns, it + 2);
        }
        stage = (stage == 2) ? 0 : stage + 1;
    }

    // epilogue
    const int cg = lane >> 2, ct = lane & 3;
    #pragma unroll
    for (int i = 0; i < 2; i++) {
        #pragma unroll
        for (int jn = 0; jn < 8; jn++) {
            int col = col0 + wn * 64 + jn * 8 + ct * 2;
            float b0 = bias[col], b1 = bias[col + 1];
            #pragma unroll
            for (int h = 0; h < 2; h++) {
                int row = row0 + wm * 32 + i * 16 + cg + h * 8;
                size_t idx = (size_t)row * N + col;
                float v0 = acc[i][jn][h * 2 + 0] + b0;
                float v1 = acc[i][jn][h * 2 + 1] + b1;
                if (EPI == 1 || EPI == 3) {
                    float2 r2 = *(const float2*)(res + idx);
                    v0 += r2.x; v1 += r2.y;
                }
                if (EPI == 2) {
                    v0 = 0.5f * v0 * (1.0f + erff(v0 * 0.7071067811865476f));
                    v1 = 0.5f * v1 * (1.0f + erff(v1 * 0.7071067811865476f));
                }
                if (CSEL == 4) {
                    *(u32*)(g_ff + idx) = pack2(f2h(v0), f2h(v1));
                } else {
                    *(float2*)(C + idx) = make_float2(v0, v1);
                }
            }
        }
    }
}

// ---------------- launcher ----------------
extern "C" void kernel_launch(void* const* d_in, const int* in_sizes, int n_in,
                              void* d_out_v, int out_size) {
    const float* q_in = (const float*)d_in[0];
    const float* s_in = (const float*)d_in[1];
    const float* Wq = (const float*)d_in[2];  const float* bq = (const float*)d_in[3];
    const float* Wk = (const float*)d_in[4];  const float* bk = (const float*)d_in[5];
    const float* Wv = (const float*)d_in[6];  const float* bv = (const float*)d_in[7];
    const float* Wh = (const float*)d_in[8];  const float* bh = (const float*)d_in[9];
    const float* lnkg = (const float*)d_in[10]; const float* lnkb = (const float*)d_in[11];
    const float* lnqg = (const float*)d_in[12]; const float* lnqb = (const float*)d_in[13];
    const float* ln2g = (const float*)d_in[14]; const float* ln2b = (const float*)d_in[15];
    const float* W1 = (const float*)d_in[16]; const float* b1 = (const float*)d_in[17];
    const float* W2 = (const float*)d_in[18]; const float* b2 = (const float*)d_in[19];
    float* out = (float*)d_out_v;

    cudaFuncSetAttribute(mma_gemm<0,0,0>, cudaFuncAttributeMaxDynamicSharedMemorySize, SMEM_DYN);
    cudaFuncSetAttribute(mma_gemm<0,1,1>, cudaFuncAttributeMaxDynamicSharedMemorySize, SMEM_DYN);
    cudaFuncSetAttribute(mma_gemm<0,1,2>, cudaFuncAttributeMaxDynamicSharedMemorySize, SMEM_DYN);
    cudaFuncSetAttribute(mma_gemm<1,0,3>, cudaFuncAttributeMaxDynamicSharedMemorySize, SMEM_DYN);
    cudaFuncSetAttribute(mma_gemm<2,1,4>, cudaFuncAttributeMaxDynamicSharedMemorySize, SMEM_DYN);
    cudaFuncSetAttribute(mma_gemm<3,2,3>, cudaFuncAttributeMaxDynamicSharedMemorySize, SMEM_DYN);

    dim3 blk(256);
    dim3 gD(DIM / 128, NE / 128);

    // Launch order arranged so launch #6 (ncu -s 5 -c 1) is a GEMM.
    wsplit_kernel<<<(512*512/4 + 255)/256, 256>>>(Wq, OFF_Q, 512*512/4);        // 1
    ln_kernel<0><<<NE, 128>>>(q_in, lnqg, lnqb);                                 // 2: ln_qry -> aq
    zero_red_kernel<<<(2 * DIM + 8 + 127) / 128, 128>>>();                       // 3
    wsplit_kernel<<<(512*512/4 + 255)/256, 256>>>(Wk, OFF_K, 512*512/4);        // 4
    wsplit_kernel<<<(512*512/4 + 255)/256, 256>>>(Wv, OFF_V, 512*512/4);        // 5
    mma_gemm<0, 0, 0><<<gD, blk, SMEM_DYN>>>(OFF_Q, bq, nullptr, nullptr, NE, DIM, DIM);  // 6: qs
    ln_kernel<1><<<NE, 128>>>(s_in, lnkg, lnkb);                                 // 7: ln_src -> as
    mma_gemm<0, 1, 1><<<gD, blk, SMEM_DYN>>>(OFF_K, bk, nullptr, nullptr, NE, DIM, DIM);  // ks
    mma_gemm<0, 1, 2><<<gD, blk, SMEM_DYN>>>(OFF_V, bv, nullptr, nullptr, NE, DIM, DIM);  // vs
    wsplit_kernel<<<(512*512/4 + 255)/256, 256>>>(Wh, OFF_H, 512*512/4);
    wsplit_kernel<<<(512*2048/4 + 255)/256, 256>>>(W1, OFF_1, 512*2048/4);
    wsplit_kernel<<<(2048*512/4 + 255)/256, 256>>>(W2, OFF_2, 2048*512/4);

    reduce_kernel<<<dim3(DIM / 128, 256), 128>>>();
    attn_kernel<<<NE, 128>>>();                    // -> aq (fp16 attn_output)

    // h_pre_ffn = source + attn @ Wh + bh -> out
    mma_gemm<1, 0, 3><<<gD, blk, SMEM_DYN>>>(OFF_H, bh, s_in, out, NE, DIM, DIM);
    // y = LN(out) -> as
    ln_kernel<1><<<NE, 128>>>(out, ln2g, ln2b);
    // ffn = gelu(y @ W1 + b1) -> g_ff (fp16)
    mma_gemm<2, 1, 4><<<dim3(DFF / 128, NE / 128), blk, SMEM_DYN>>>(OFF_1, b1, nullptr, nullptr, NE, DFF, DIM);
    // out = out + ffn @ W2 + b2
    mma_gemm<3, 2, 3><<<gD, blk, SMEM_DYN>>>(OFF_2, b2, out, out, NE, DIM, DFF);
}

// round 14
// speedup vs baseline: 5.6158x; 1.4169x over previous
#include <cuda_runtime.h>
#include <math.h>

#define NE   65536
#define DIM  512
#define DFF  2048
#define LN_EPS 1e-5f

typedef unsigned short u16;
typedef unsigned int   u32;

// ---------------- scratch (device globals; no allocations) ----------------
__device__ __align__(16) float g_qs [(size_t)NE * DIM];
__device__ __align__(16) float g_ks [(size_t)NE * DIM];
__device__ __align__(16) float g_vs [(size_t)NE * DIM];
// single-fp16 activations
__device__ __align__(16) u16 g_aq[(size_t)NE * DIM];   // ln_qry, later attn_output
__device__ __align__(16) u16 g_as[(size_t)NE * DIM];   // ln_src, later y (ln2 out)
__device__ __align__(16) u16 g_ff[(size_t)NE * DFF];   // gelu output
// weights single fp16
#define OFF_Q 0
#define OFF_K (512*512)
#define OFF_V (2*512*512)
#define OFF_H (3*512*512)
#define OFF_1 (4*512*512)
#define OFF_2 (4*512*512 + 512*2048)
#define W_TOT (4*512*512 + 2*512*2048)
__device__ __align__(16) u16 g_w[W_TOT];
// [0,DIM)=diag  [DIM,2DIM)=ksum  [2DIM]=|qs|^2  [2DIM+1]=|ks|^2
__device__ __align__(16) float g_red[2 * DIM + 8];

// ---------------- fp16-as-bits helpers ----------------
__device__ __forceinline__ u16 f2h(float x) {
    u16 h;
    asm("cvt.rn.f16.f32 %0, %1;" : "=h"(h) : "f"(x));
    return h;
}
__device__ __forceinline__ u32 pack2(u16 a, u16 b) {
    return (u32)a | ((u32)b << 16);
}

__device__ __forceinline__ u32 smem_u32(const void* p) {
    return (u32)__cvta_generic_to_shared(p);
}
__device__ __forceinline__ void ldsm_x4(u32* r, u32 a) {
    asm volatile("ldmatrix.sync.aligned.m8n8.x4.shared.b16 {%0,%1,%2,%3}, [%4];"
                 : "=r"(r[0]), "=r"(r[1]), "=r"(r[2]), "=r"(r[3]) : "r"(a));
}
__device__ __forceinline__ void ldsm_x4t(u32* r, u32 a) {
    asm volatile("ldmatrix.sync.aligned.m8n8.x4.trans.shared.b16 {%0,%1,%2,%3}, [%4];"
                 : "=r"(r[0]), "=r"(r[1]), "=r"(r[2]), "=r"(r[3]) : "r"(a));
}
__device__ __forceinline__ void mma16816(float* d, const u32* a, const u32* b) {
    asm volatile("mma.sync.aligned.m16n8k16.row.col.f32.f16.f16.f32 "
                 "{%0,%1,%2,%3}, {%4,%5,%6,%7}, {%8,%9}, {%0,%1,%2,%3};"
                 : "+f"(d[0]), "+f"(d[1]), "+f"(d[2]), "+f"(d[3])
                 : "r"(a[0]), "r"(a[1]), "r"(a[2]), "r"(a[3]), "r"(b[0]), "r"(b[1]));
}
__device__ __forceinline__ void cpa16(u32 dst, const void* src) {
    asm volatile("cp.async.cg.shared.global [%0], [%1], 16;" :: "r"(dst), "l"(src));
}
__device__ __forceinline__ void cp_commit() {
    asm volatile("cp.async.commit_group;");
}
template <int N>
__device__ __forceinline__ void cp_wait() {
    asm volatile("cp.async.wait_group %0;" :: "n"(N));
}

// ---------------- small kernels ----------------
__global__ void zero_red_kernel() {
    int i = blockIdx.x * blockDim.x + threadIdx.x;
    if (i < 2 * DIM + 8) g_red[i] = 0.0f;
}

__global__ void wsplit_kernel(const float* __restrict__ src, int off, int n4) {
    int i = blockIdx.x * 256 + threadIdx.x;
    if (i < n4) {
        float4 v = ((const float4*)src)[i];
        size_t o = (size_t)off + (size_t)i * 4;
        *(u32*)(g_w + o)     = pack2(f2h(v.x), f2h(v.y));
        *(u32*)(g_w + o + 2) = pack2(f2h(v.z), f2h(v.w));
    }
}

// layernorm -> single fp16.  DST: 0 -> g_aq, 1 -> g_as
template <int DST>
__global__ void ln_kernel(const float* __restrict__ x,
                          const float* __restrict__ gamma, const float* __restrict__ beta) {
    u16* y = (DST == 0) ? g_aq : g_as;
    int row = blockIdx.x;
    int t = threadIdx.x;
    const float4* xin = (const float4*)(x + (size_t)row * DIM);
    float4 v = xin[t];
    float s1 = v.x + v.y + v.z + v.w;
    float s2 = v.x*v.x + v.y*v.y + v.z*v.z + v.w*v.w;
    #pragma unroll
    for (int o = 16; o; o >>= 1) {
        s1 += __shfl_xor_sync(0xffffffffu, s1, o);
        s2 += __shfl_xor_sync(0xffffffffu, s2, o);
    }
    __shared__ float sh1[4], sh2[4];
    int w = t >> 5;
    if ((t & 31) == 0) { sh1[w] = s1; sh2[w] = s2; }
    __syncthreads();
    s1 = sh1[0] + sh1[1] + sh1[2] + sh1[3];
    s2 = sh2[0] + sh2[1] + sh2[2] + sh2[3];
    float mean = s1 * (1.0f / DIM);
    float var  = s2 * (1.0f / DIM) - mean * mean;
    float rstd = rsqrtf(var + LN_EPS);
    float4 gg = ((const float4*)gamma)[t];
    float4 bb = ((const float4*)beta)[t];
    float o0 = (v.x - mean) * rstd * gg.x + bb.x;
    float o1 = (v.y - mean) * rstd * gg.y + bb.y;
    float o2 = (v.z - mean) * rstd * gg.z + bb.z;
    float o3 = (v.w - mean) * rstd * gg.w + bb.w;
    size_t off = (size_t)row * DIM + t * 4;
    *(u32*)(y + off)     = pack2(f2h(o0), f2h(o1));
    *(u32*)(y + off + 2) = pack2(f2h(o2), f2h(o3));
}

// column reductions over qs/ks/vs
__global__ void reduce_kernel() {
    int c = blockIdx.x * 128 + threadIdx.x;
    int r0 = blockIdx.y * 256;
    float sd = 0.f, sk = 0.f, sk2 = 0.f, sq2 = 0.f;
    for (int r = 0; r < 256; r++) {
        size_t idx = (size_t)(r0 + r) * DIM + c;
        float kk = g_ks[idx], vv = g_vs[idx], qq = g_qs[idx];
        sd += kk * vv; sk += kk; sk2 += kk * kk; sq2 += qq * qq;
    }
    atomicAdd(&g_red[c], sd);
    atomicAdd(&g_red[DIM + c], sk);
    #pragma unroll
    for (int o = 16; o; o >>= 1) {
        sq2 += __shfl_xor_sync(0xffffffffu, sq2, o);
        sk2 += __shfl_xor_sync(0xffffffffu, sk2, o);
    }
    __shared__ float sa[4], sb[4];
    if ((threadIdx.x & 31) == 0) { sa[threadIdx.x >> 5] = sq2; sb[threadIdx.x >> 5] = sk2; }
    __syncthreads();
    if (threadIdx.x == 0) {
        atomicAdd(&g_red[2 * DIM],     sa[0] + sa[1] + sa[2] + sa[3]);
        atomicAdd(&g_red[2 * DIM + 1], sb[0] + sb[1] + sb[2] + sb[3]);
    }
}

// attention finalize -> single fp16 into g_aq
__global__ void attn_kernel() {
    int row = blockIdx.x;
    int t = threadIdx.x;  // cols 4t..4t+3; head = t/16
    float rFq = rsqrtf(g_red[2 * DIM]);
    float rFk = rsqrtf(g_red[2 * DIM + 1]);
    const float nf = (float)NE;
    size_t base = (size_t)row * DIM;
    float4 q  = ((const float4*)(g_qs + base))[t];
    float4 v  = ((const float4*)(g_vs + base))[t];
    float4 dg = ((const float4*)(g_red))[t];
    float4 km = ((const float4*)(g_red + DIM))[t];
    float p = (q.x*km.x + q.y*km.y + q.z*km.z + q.w*km.w) * (rFq * rFk);
    #pragma unroll
    for (int o = 8; o; o >>= 1) p += __shfl_xor_sync(0xffffffffu, p, o);
    float inv = 1.0f / (p + nf);
    float s = rFq * rFk;
    float o0 = (q.x * s * dg.x + v.x * nf) * inv;
    float o1 = (q.y * s * dg.y + v.y * nf) * inv;
    float o2 = (q.z * s * dg.z + v.z * nf) * inv;
    float o3 = (q.w * s * dg.w + v.w * nf) * inv;
    size_t off = base + t * 4;
    *(u32*)(g_aq + off)     = pack2(f2h(o0), f2h(o1));
    *(u32*)(g_aq + off + 2) = pack2(f2h(o2), f2h(o3));
}

// ---------------- single-fp16 tensor-core GEMM, 3-stage cp.async, 1 sync/slab ----------------
// C = A@B, both single fp16 (A err ~2.8e-4, B err ~1.5e-4 rel; measured-anchored).
// ASEL: 0 -> g_aq, 1 -> g_as, 2 -> g_ff     CSEL: 0 qs, 1 ks, 2 vs, 3 Carg, 4 g_ff(fp16)
// EPI 0: +bias   EPI 1: +bias+res   EPI 2: gelu(+bias)   EPI 3: +bias+res (res==Carg ok)
// Stage (bytes): A[128x32]@0 (8K), B[32x128]@8192 (8K).  16KB/stage.
#define STG_BYTES 16384
#define SMEM_DYN (3 * STG_BYTES)
template <int EPI, int ASEL, int CSEL>
__global__ void __launch_bounds__(256)
mma_gemm(int boff, const float* __restrict__ bias, const float* __restrict__ res,
         float* __restrict__ Carg, int M, int N, int K)
{
    const u16* A = (ASEL == 0) ? g_aq : (ASEL == 1) ? g_as : g_ff;
    const u16* B = g_w + boff;
    float* C = (CSEL == 0) ? g_qs : (CSEL == 1) ? g_ks : (CSEL == 2) ? g_vs : Carg;

    extern __shared__ __align__(16) u16 smem[];
    const int tid = threadIdx.x, lane = tid & 31, warp = tid >> 5;
    const int wm = warp >> 1, wn = warp & 1;            // 4 x 2 warp grid, 32x64
    const int row0 = blockIdx.y * 128;
    const int col0 = blockIdx.x * 128;

    float acc[2][8][4];
    #pragma unroll
    for (int i = 0; i < 2; i++)
        #pragma unroll
        for (int j = 0; j < 8; j++)
            #pragma unroll
            for (int c = 0; c < 4; c++) acc[i][j][c] = 0.0f;

    const u32 sBase = smem_u32(smem);

    const int lrA = lane & 15, lgA = lane >> 4;
    const int lkB = (lane & 7) + ((lane >> 3) & 1) * 8;
    const int lgB = lane >> 4;
    const int ar = tid >> 2, aq = tid & 3;
    const int br = tid >> 4, bq = tid & 15;

    // per-thread smem dst offsets (bytes, relative to stage base)
    u32 dA0 = (u32)((ar)      * 32 + 8 * (aq ^ (((ar)      >> 1) & 3))) * 2;
    u32 dA1 = (u32)((ar + 64) * 32 + 8 * (aq ^ (((ar + 64) >> 1) & 3))) * 2;
    u32 dB0 = (u32)((br)      * 128 + 8 * (bq ^ ((br)      & 7))) * 2 + 8192;
    u32 dB1 = (u32)((br + 16) * 128 + 8 * (bq ^ ((br + 16) & 7))) * 2 + 8192;

    const int nk = K >> 5;  // K/32 slabs (16 or 64)

    auto load_stage = [&](int stage, int slab) {
        int k0 = slab << 5;
        u32 sb = sBase + stage * STG_BYTES;
        const u16* a0 = A + (size_t)(row0 + ar) * K + k0 + aq * 8;
        const u16* a1 = A + (size_t)(row0 + ar + 64) * K + k0 + aq * 8;
        cpa16(sb + dA0, a0);
        cpa16(sb + dA1, a1);
        const u16* b0 = B + (size_t)(k0 + br) * N + col0 + bq * 8;
        const u16* b1 = B + (size_t)(k0 + br + 16) * N + col0 + bq * 8;
        cpa16(sb + dB0, b0);
        cpa16(sb + dB1, b1);
        cp_commit();
    };

    // prologue: 2 stages in flight
    load_stage(0, 0);
    load_stage(1, 1);

    int stage = 0;
    for (int it = 0; it < nk; it++) {
        if (it + 1 < nk) cp_wait<1>(); else cp_wait<0>();
        __syncthreads();   // single barrier per slab

        const u32 stA = sBase + stage * STG_BYTES;
        const u32 stB = stA + 8192;
        #pragma unroll
        for (int ks = 0; ks < 32; ks += 16) {
            u32 ahf[2][4];
            #pragma unroll
            for (int i = 0; i < 2; i++) {
                int r = wm * 32 + i * 16 + lrA;
                int G = (ks >> 3) + lgA;
                u32 off = (u32)(r * 32 + 8 * (G ^ ((r >> 1) & 3))) * 2;
                ldsm_x4(ahf[i], stA + off);
            }
            int kB = ks + lkB;
            int swb = kB & 7;
            #pragma unroll
            for (int jp = 0; jp < 4; jp++) {
                int G = wn * 8 + jp * 2 + lgB;
                u32 off = (u32)(kB * 128 + 8 * (G ^ swb)) * 2;
                u32 bhf[4];
                ldsm_x4t(bhf, stB + off);
                #pragma unroll
                for (int i = 0; i < 2; i++) {
                    #pragma unroll
                    for (int jj = 0; jj < 2; jj++) {
                        mma16816(acc[i][jp * 2 + jj], ahf[i], bhf + 2 * jj);
                    }
                }
            }
        }
        // refill the stage consumed 2 iterations ago; no trailing barrier needed.
        if (it + 2 < nk) {
            int ns = stage + 2;
            if (ns >= 3) ns -= 3;
            load_stage(ns, it + 2);
        }
        stage = (stage == 2) ? 0 : stage + 1;
    }

    // epilogue
    const int cg = lane >> 2, ct = lane & 3;
    #pragma unroll
    for (int i = 0; i < 2; i++) {
        #pragma unroll
        for (int jn = 0; jn < 8; jn++) {
            int col = col0 + wn * 64 + jn * 8 + ct * 2;
            float b0 = bias[col], b1 = bias[col + 1];
            #pragma unroll
            for (int h = 0; h < 2; h++) {
                int row = row0 + wm * 32 + i * 16 + cg + h * 8;
                size_t idx = (size_t)row * N + col;
                float v0 = acc[i][jn][h * 2 + 0] + b0;
                float v1 = acc[i][jn][h * 2 + 1] + b1;
                if (EPI == 1 || EPI == 3) {
                    float2 r2 = *(const float2*)(res + idx);
                    v0 += r2.x; v1 += r2.y;
                }
                if (EPI == 2) {
                    v0 = 0.5f * v0 * (1.0f + erff(v0 * 0.7071067811865476f));
                    v1 = 0.5f * v1 * (1.0f + erff(v1 * 0.7071067811865476f));
                }
                if (CSEL == 4) {
                    *(u32*)(g_ff + idx) = pack2(f2h(v0), f2h(v1));
                } else {
                    *(float2*)(C + idx) = make_float2(v0, v1);
                }
            }
        }
    }
}

// ---------------- launcher ----------------
extern "C" void kernel_launch(void* const* d_in, const int* in_sizes, int n_in,
                              void* d_out_v, int out_size) {
    const float* q_in = (const float*)d_in[0];
    const float* s_in = (const float*)d_in[1];
    const float* Wq = (const float*)d_in[2];  const float* bq = (const float*)d_in[3];
    const float* Wk = (const float*)d_in[4];  const float* bk = (const float*)d_in[5];
    const float* Wv = (const float*)d_in[6];  const float* bv = (const float*)d_in[7];
    const float* Wh = (const float*)d_in[8];  const float* bh = (const float*)d_in[9];
    const float* lnkg = (const float*)d_in[10]; const float* lnkb = (const float*)d_in[11];
    const float* lnqg = (const float*)d_in[12]; const float* lnqb = (const float*)d_in[13];
    const float* ln2g = (const float*)d_in[14]; const float* ln2b = (const float*)d_in[15];
    const float* W1 = (const float*)d_in[16]; const float* b1 = (const float*)d_in[17];
    const float* W2 = (const float*)d_in[18]; const float* b2 = (const float*)d_in[19];
    float* out = (float*)d_out_v;

    cudaFuncSetAttribute(mma_gemm<0,0,0>, cudaFuncAttributeMaxDynamicSharedMemorySize, SMEM_DYN);
    cudaFuncSetAttribute(mma_gemm<0,1,1>, cudaFuncAttributeMaxDynamicSharedMemorySize, SMEM_DYN);
    cudaFuncSetAttribute(mma_gemm<0,1,2>, cudaFuncAttributeMaxDynamicSharedMemorySize, SMEM_DYN);
    cudaFuncSetAttribute(mma_gemm<1,0,3>, cudaFuncAttributeMaxDynamicSharedMemorySize, SMEM_DYN);
    cudaFuncSetAttribute(mma_gemm<2,1,4>, cudaFuncAttributeMaxDynamicSharedMemorySize, SMEM_DYN);
    cudaFuncSetAttribute(mma_gemm<3,2,3>, cudaFuncAttributeMaxDynamicSharedMemorySize, SMEM_DYN);

    dim3 blk(256);
    dim3 gD(DIM / 128, NE / 128);

    // Launch order arranged so launch #6 (ncu -s 5 -c 1) is a GEMM.
    wsplit_kernel<<<(512*512/4 + 255)/256, 256>>>(Wq, OFF_Q, 512*512/4);        // 1
    ln_kernel<0><<<NE, 128>>>(q_in, lnqg, lnqb);                                 // 2: ln_qry -> aq
    zero_red_kernel<<<(2 * DIM + 8 + 127) / 128, 128>>>();                       // 3
    wsplit_kernel<<<(512*512/4 + 255)/256, 256>>>(Wk, OFF_K, 512*512/4);        // 4
    wsplit_kernel<<<(512*512/4 + 255)/256, 256>>>(Wv, OFF_V, 512*512/4);        // 5
    mma_gemm<0, 0, 0><<<gD, blk, SMEM_DYN>>>(OFF_Q, bq, nullptr, nullptr, NE, DIM, DIM);  // 6: qs
    ln_kernel<1><<<NE, 128>>>(s_in, lnkg, lnkb);                                 // 7: ln_src -> as
    mma_gemm<0, 1, 1><<<gD, blk, SMEM_DYN>>>(OFF_K, bk, nullptr, nullptr, NE, DIM, DIM);  // ks
    mma_gemm<0, 1, 2><<<gD, blk, SMEM_DYN>>>(OFF_V, bv, nullptr, nullptr, NE, DIM, DIM);  // vs
    wsplit_kernel<<<(512*512/4 + 255)/256, 256>>>(Wh, OFF_H, 512*512/4);
    wsplit_kernel<<<(512*2048/4 + 255)/256, 256>>>(W1, OFF_1, 512*2048/4);
    wsplit_kernel<<<(2048*512/4 + 255)/256, 256>>>(W2, OFF_2, 2048*512/4);

    reduce_kernel<<<dim3(DIM / 128, 256), 128>>>();
    attn_kernel<<<NE, 128>>>();                    // -> aq (fp16 attn_output)

    // h_pre_ffn = source + attn @ Wh + bh -> out
    mma_gemm<1, 0, 3><<<gD, blk, SMEM_DYN>>>(OFF_H, bh, s_in, out, NE, DIM, DIM);
    // y = LN(out) -> as
    ln_kernel<1><<<NE, 128>>>(out, ln2g, ln2b);
    // ffn = gelu(y @ W1 + b1) -> g_ff (fp16)
    mma_gemm<2, 1, 4><<<dim3(DFF / 128, NE / 128), blk, SMEM_DYN>>>(OFF_1, b1, nullptr, nullptr, NE, DFF, DIM);
    // out = out + ffn @ W2 + b2
    mma_gemm<3, 2, 3><<<gD, blk, SMEM_DYN>>>(OFF_2, b2, out, out, NE, DIM, DFF);
}

// round 15
// speedup vs baseline: 5.7470x; 1.0234x over previous
#include <cuda_runtime.h>
#include <math.h>

#define NE   65536
#define DIM  512
#define DFF  2048
#define LN_EPS 1e-5f

typedef unsigned short u16;
typedef unsigned int   u32;

// ---------------- scratch (device globals; no allocations) ----------------
__device__ __align__(16) u16 g_q16[(size_t)NE * DIM];  // qs (fp16, from Q gemm epilogue)
__device__ __align__(16) u16 g_v16[(size_t)NE * DIM];  // vs (fp16, from KV gemm epilogue)
__device__ __align__(16) u16 g_aq[(size_t)NE * DIM];   // ln_qry, later attn_output
__device__ __align__(16) u16 g_as[(size_t)NE * DIM];   // ln_src, later y (ln2 out)
__device__ __align__(16) u16 g_ff[(size_t)NE * DFF];   // gelu output
// weights single fp16;  KV interleaved: col 2d = Wk[:,d], col 2d+1 = Wv[:,d]
#define OFF_Q 0
#define OFF_KV (512*512)
#define OFF_H (3*512*512)
#define OFF_1 (4*512*512)
#define OFF_2 (4*512*512 + 512*2048)
#define W_TOT (4*512*512 + 2*512*2048)
__device__ __align__(16) u16 g_w[W_TOT];
// [0,DIM)=diag_raw  [DIM,2DIM)=ksum_raw  [2DIM]=|qs|^2  [2DIM+1]=|ks|^2
__device__ __align__(16) float g_red[2 * DIM + 8];

// ---------------- fp16-as-bits helpers ----------------
__device__ __forceinline__ u16 f2h(float x) {
    u16 h;
    asm("cvt.rn.f16.f32 %0, %1;" : "=h"(h) : "f"(x));
    return h;
}
__device__ __forceinline__ float h2f(u16 h) {
    float f;
    asm("cvt.f32.f16 %0, %1;" : "=f"(f) : "h"(h));
    return f;
}
__device__ __forceinline__ u32 pack2(u16 a, u16 b) {
    return (u32)a | ((u32)b << 16);
}

__device__ __forceinline__ u32 smem_u32(const void* p) {
    return (u32)__cvta_generic_to_shared(p);
}
__device__ __forceinline__ void ldsm_x4(u32* r, u32 a) {
    asm volatile("ldmatrix.sync.aligned.m8n8.x4.shared.b16 {%0,%1,%2,%3}, [%4];"
                 : "=r"(r[0]), "=r"(r[1]), "=r"(r[2]), "=r"(r[3]) : "r"(a));
}
__device__ __forceinline__ void ldsm_x4t(u32* r, u32 a) {
    asm volatile("ldmatrix.sync.aligned.m8n8.x4.trans.shared.b16 {%0,%1,%2,%3}, [%4];"
                 : "=r"(r[0]), "=r"(r[1]), "=r"(r[2]), "=r"(r[3]) : "r"(a));
}
__device__ __forceinline__ void mma16816(float* d, const u32* a, const u32* b) {
    asm volatile("mma.sync.aligned.m16n8k16.row.col.f32.f16.f16.f32 "
                 "{%0,%1,%2,%3}, {%4,%5,%6,%7}, {%8,%9}, {%0,%1,%2,%3};"
                 : "+f"(d[0]), "+f"(d[1]), "+f"(d[2]), "+f"(d[3])
                 : "r"(a[0]), "r"(a[1]), "r"(a[2]), "r"(a[3]), "r"(b[0]), "r"(b[1]));
}
__device__ __forceinline__ void cpa16(u32 dst, const void* src) {
    asm volatile("cp.async.cg.shared.global [%0], [%1], 16;" :: "r"(dst), "l"(src));
}
__device__ __forceinline__ void cp_commit() {
    asm volatile("cp.async.commit_group;");
}
template <int N>
__device__ __forceinline__ void cp_wait() {
    asm volatile("cp.async.wait_group %0;" :: "n"(N));
}

// ---------------- small kernels ----------------
__global__ void zero_red_kernel() {
    int i = blockIdx.x * blockDim.x + threadIdx.x;
    if (i < 2 * DIM + 8) g_red[i] = 0.0f;
}

__global__ void wsplit_kernel(const float* __restrict__ src, int off, int n4) {
    int i = blockIdx.x * 256 + threadIdx.x;
    if (i < n4) {
        float4 v = ((const float4*)src)[i];
        size_t o = (size_t)off + (size_t)i * 4;
        *(u32*)(g_w + o)     = pack2(f2h(v.x), f2h(v.y));
        *(u32*)(g_w + o + 2) = pack2(f2h(v.z), f2h(v.w));
    }
}

// interleave Wk|Wv -> g_w[OFF_KV + k*1024 + 2d(+1)]
__global__ void wsplit_kv_kernel(const float* __restrict__ Wk, const float* __restrict__ Wv) {
    int i = blockIdx.x * 256 + threadIdx.x;   // over 512*512/4
    if (i < 512 * 512 / 4) {
        int k = i >> 7, dq = i & 127;         // d0 = dq*4
        float4 a = ((const float4*)(Wk + (size_t)k * 512))[dq];
        float4 b = ((const float4*)(Wv + (size_t)k * 512))[dq];
        size_t o = (size_t)OFF_KV + (size_t)k * 1024 + dq * 8;
        *(u32*)(g_w + o)     = pack2(f2h(a.x), f2h(b.x));
        *(u32*)(g_w + o + 2) = pack2(f2h(a.y), f2h(b.y));
        *(u32*)(g_w + o + 4) = pack2(f2h(a.z), f2h(b.z));
        *(u32*)(g_w + o + 6) = pack2(f2h(a.w), f2h(b.w));
    }
}

// layernorm -> single fp16.  DST: 0 -> g_aq, 1 -> g_as
template <int DST>
__global__ void ln_kernel(const float* __restrict__ x,
                          const float* __restrict__ gamma, const float* __restrict__ beta) {
    u16* y = (DST == 0) ? g_aq : g_as;
    int row = blockIdx.x;
    int t = threadIdx.x;
    const float4* xin = (const float4*)(x + (size_t)row * DIM);
    float4 v = xin[t];
    float s1 = v.x + v.y + v.z + v.w;
    float s2 = v.x*v.x + v.y*v.y + v.z*v.z + v.w*v.w;
    #pragma unroll
    for (int o = 16; o; o >>= 1) {
        s1 += __shfl_xor_sync(0xffffffffu, s1, o);
        s2 += __shfl_xor_sync(0xffffffffu, s2, o);
    }
    __shared__ float sh1[4], sh2[4];
    int w = t >> 5;
    if ((t & 31) == 0) { sh1[w] = s1; sh2[w] = s2; }
    __syncthreads();
    s1 = sh1[0] + sh1[1] + sh1[2] + sh1[3];
    s2 = sh2[0] + sh2[1] + sh2[2] + sh2[3];
    float mean = s1 * (1.0f / DIM);
    float var  = s2 * (1.0f / DIM) - mean * mean;
    float rstd = rsqrtf(var + LN_EPS);
    float4 gg = ((const float4*)gamma)[t];
    float4 bb = ((const float4*)beta)[t];
    float o0 = (v.x - mean) * rstd * gg.x + bb.x;
    float o1 = (v.y - mean) * rstd * gg.y + bb.y;
    float o2 = (v.z - mean) * rstd * gg.z + bb.z;
    float o3 = (v.w - mean) * rstd * gg.w + bb.w;
    size_t off = (size_t)row * DIM + t * 4;
    *(u32*)(y + off)     = pack2(f2h(o0), f2h(o1));
    *(u32*)(y + off + 2) = pack2(f2h(o2), f2h(o3));
}

// attention finalize: reads g_q16/g_v16 + g_red, writes fp16 attn_output to g_aq
__global__ void attn_kernel() {
    int row = blockIdx.x;
    int t = threadIdx.x;  // cols 4t..4t+3; head = t/16
    float rFq = rsqrtf(g_red[2 * DIM]);
    float rFk = rsqrtf(g_red[2 * DIM + 1]);
    const float nf = (float)NE;
    size_t base = (size_t)row * DIM;
    u32 qa = ((const u32*)(g_q16 + base))[2 * t];
    u32 qb = ((const u32*)(g_q16 + base))[2 * t + 1];
    u32 va = ((const u32*)(g_v16 + base))[2 * t];
    u32 vb = ((const u32*)(g_v16 + base))[2 * t + 1];
    float q0 = h2f((u16)(qa & 0xFFFF)), q1 = h2f((u16)(qa >> 16));
    float q2 = h2f((u16)(qb & 0xFFFF)), q3 = h2f((u16)(qb >> 16));
    float v0 = h2f((u16)(va & 0xFFFF)), v1 = h2f((u16)(va >> 16));
    float v2 = h2f((u16)(vb & 0xFFFF)), v3 = h2f((u16)(vb >> 16));
    float4 dg = ((const float4*)(g_red))[t];
    float4 km = ((const float4*)(g_red + DIM))[t];
    float p = (q0*km.x + q1*km.y + q2*km.z + q3*km.w) * (rFq * rFk);
    #pragma unroll
    for (int o = 8; o; o >>= 1) p += __shfl_xor_sync(0xffffffffu, p, o);
    float inv = 1.0f / (p + nf);
    float s = rFq * rFk;
    float o0 = (q0 * s * dg.x + v0 * nf) * inv;
    float o1 = (q1 * s * dg.y + v1 * nf) * inv;
    float o2 = (q2 * s * dg.z + v2 * nf) * inv;
    float o3 = (q3 * s * dg.w + v3 * nf) * inv;
    size_t off = base + t * 4;
    *(u32*)(g_aq + off)     = pack2(f2h(o0), f2h(o1));
    *(u32*)(g_aq + off + 2) = pack2(f2h(o2), f2h(o3));
}

// ---------------- single-fp16 tensor-core GEMM, 3-stage cp.async, 1 sync/slab ----------------
// ASEL: 0 -> g_aq, 1 -> g_as, 2 -> g_ff
// EPI 1: +bias+res -> Carg     EPI 2: gelu(+bias) -> g_ff(fp16)   EPI 3: +bias+res -> Carg
// EPI 4: Q  (+bias -> g_q16 fp16, accumulate |qs|^2)
// EPI 5: KV (interleaved cols; compute diag/ksum/|ks|^2, store vs fp16; nothing else written)
// Stage (bytes): A[128x32]@0 (8K), B[32x128]@8192 (8K).  16KB/stage.
#define STG_BYTES 16384
#define SMEM_DYN (3 * STG_BYTES)
template <int EPI, int ASEL>
__global__ void __launch_bounds__(256)
mma_gemm(int boff, const float* __restrict__ bias, const float* __restrict__ bias2,
         const float* __restrict__ res, float* __restrict__ Carg, int M, int N, int K)
{
    const u16* A = (ASEL == 0) ? g_aq : (ASEL == 1) ? g_as : g_ff;
    const u16* B = g_w + boff;

    extern __shared__ __align__(16) u16 smem[];
    const int tid = threadIdx.x, lane = tid & 31, warp = tid >> 5;
    const int wm = warp >> 1, wn = warp & 1;            // 4 x 2 warp grid, 32x64
    const int row0 = blockIdx.y * 128;
    const int col0 = blockIdx.x * 128;

    float acc[2][8][4];
    #pragma unroll
    for (int i = 0; i < 2; i++)
        #pragma unroll
        for (int j = 0; j < 8; j++)
            #pragma unroll
            for (int c = 0; c < 4; c++) acc[i][j][c] = 0.0f;

    const u32 sBase = smem_u32(smem);

    const int lrA = lane & 15, lgA = lane >> 4;
    const int lkB = (lane & 7) + ((lane >> 3) & 1) * 8;
    const int lgB = lane >> 4;
    const int ar = tid >> 2, aq = tid & 3;
    const int br = tid >> 4, bq = tid & 15;

    u32 dA0 = (u32)((ar)      * 32 + 8 * (aq ^ (((ar)      >> 1) & 3))) * 2;
    u32 dA1 = (u32)((ar + 64) * 32 + 8 * (aq ^ (((ar + 64) >> 1) & 3))) * 2;
    u32 dB0 = (u32)((br)      * 128 + 8 * (bq ^ ((br)      & 7))) * 2 + 8192;
    u32 dB1 = (u32)((br + 16) * 128 + 8 * (bq ^ ((br + 16) & 7))) * 2 + 8192;

    const int nk = K >> 5;

    auto load_stage = [&](int stage, int slab) {
        int k0 = slab << 5;
        u32 sb = sBase + stage * STG_BYTES;
        const u16* a0 = A + (size_t)(row0 + ar) * K + k0 + aq * 8;
        const u16* a1 = A + (size_t)(row0 + ar + 64) * K + k0 + aq * 8;
        cpa16(sb + dA0, a0);
        cpa16(sb + dA1, a1);
        const u16* b0 = B + (size_t)(k0 + br) * N + col0 + bq * 8;
        const u16* b1 = B + (size_t)(k0 + br + 16) * N + col0 + bq * 8;
        cpa16(sb + dB0, b0);
        cpa16(sb + dB1, b1);
        cp_commit();
    };

    load_stage(0, 0);
    load_stage(1, 1);

    int stage = 0;
    for (int it = 0; it < nk; it++) {
        if (it + 1 < nk) cp_wait<1>(); else cp_wait<0>();
        __syncthreads();

        const u32 stA = sBase + stage * STG_BYTES;
        const u32 stB = stA + 8192;
        #pragma unroll
        for (int ks = 0; ks < 32; ks += 16) {
            u32 ahf[2][4];
            #pragma unroll
            for (int i = 0; i < 2; i++) {
                int r = wm * 32 + i * 16 + lrA;
                int G = (ks >> 3) + lgA;
                u32 off = (u32)(r * 32 + 8 * (G ^ ((r >> 1) & 3))) * 2;
                ldsm_x4(ahf[i], stA + off);
            }
            int kB = ks + lkB;
            int swb = kB & 7;
            #pragma unroll
            for (int jp = 0; jp < 4; jp++) {
                int G = wn * 8 + jp * 2 + lgB;
                u32 off = (u32)(kB * 128 + 8 * (G ^ swb)) * 2;
                u32 bhf[4];
                ldsm_x4t(bhf, stB + off);
                #pragma unroll
                for (int i = 0; i < 2; i++) {
                    #pragma unroll
                    for (int jj = 0; jj < 2; jj++) {
                        mma16816(acc[i][jp * 2 + jj], ahf[i], bhf + 2 * jj);
                    }
                }
            }
        }
        if (it + 2 < nk) {
            int ns = stage + 2;
            if (ns >= 3) ns -= 3;
            load_stage(ns, it + 2);
        }
        stage = (stage == 2) ? 0 : stage + 1;
    }

    const int cg = lane >> 2, ct = lane & 3;

    if (EPI <= 3) {
        // standard epilogues
        #pragma unroll
        for (int i = 0; i < 2; i++) {
            #pragma unroll
            for (int jn = 0; jn < 8; jn++) {
                int col = col0 + wn * 64 + jn * 8 + ct * 2;
                float b0 = bias[col], b1 = bias[col + 1];
                #pragma unroll
                for (int h = 0; h < 2; h++) {
                    int row = row0 + wm * 32 + i * 16 + cg + h * 8;
                    size_t idx = (size_t)row * N + col;
                    float v0 = acc[i][jn][h * 2 + 0] + b0;
                    float v1 = acc[i][jn][h * 2 + 1] + b1;
                    if (EPI == 1 || EPI == 3) {
                        float2 r2 = *(const float2*)(res + idx);
                        v0 += r2.x; v1 += r2.y;
                    }
                    if (EPI == 2) {
                        v0 = 0.5f * v0 * (1.0f + erff(v0 * 0.7071067811865476f));
                        v1 = 0.5f * v1 * (1.0f + erff(v1 * 0.7071067811865476f));
                        *(u32*)(g_ff + idx) = pack2(f2h(v0), f2h(v1));
                    } else {
                        *(float2*)(Carg + idx) = make_float2(v0, v1);
                    }
                }
            }
        }
    } else if (EPI == 4) {
        // Q: store fp16 + accumulate |qs|^2
        float sq2 = 0.0f;
        #pragma unroll
        for (int i = 0; i < 2; i++) {
            #pragma unroll
            for (int jn = 0; jn < 8; jn++) {
                int col = col0 + wn * 64 + jn * 8 + ct * 2;
                float b0 = bias[col], b1 = bias[col + 1];
                #pragma unroll
                for (int h = 0; h < 2; h++) {
                    int row = row0 + wm * 32 + i * 16 + cg + h * 8;
                    size_t idx = (size_t)row * N + col;
                    float v0 = acc[i][jn][h * 2 + 0] + b0;
                    float v1 = acc[i][jn][h * 2 + 1] + b1;
                    sq2 += v0 * v0 + v1 * v1;
                    *(u32*)(g_q16 + idx) = pack2(f2h(v0), f2h(v1));
                }
            }
        }
        #pragma unroll
        for (int o = 16; o; o >>= 1) sq2 += __shfl_xor_sync(0xffffffffu, sq2, o);
        if (lane == 0) atomicAdd(&g_red[2 * DIM], sq2);
    } else {
        // KV: interleaved cols (even=ks, odd=vs). diag/ksum/|ks|^2 + store vs fp16.
        float* sdS = (float*)smem;          // [64]
        float* skS = sdS + 64;              // [64]
        __syncthreads();
        if (tid < 64) { sdS[tid] = 0.0f; skS[tid] = 0.0f; }
        __syncthreads();

        float sd_loc[8], sk_loc[8], sk2 = 0.0f;
        #pragma unroll
        for (int jn = 0; jn < 8; jn++) { sd_loc[jn] = 0.0f; sk_loc[jn] = 0.0f; }
        #pragma unroll
        for (int i = 0; i < 2; i++) {
            #pragma unroll
            for (int jn = 0; jn < 8; jn++) {
                int col = col0 + wn * 64 + jn * 8 + ct * 2;   // even
                int d = col >> 1;
                float bk_ = bias[d], bv_ = bias2[d];
                #pragma unroll
                for (int h = 0; h < 2; h++) {
                    int row = row0 + wm * 32 + i * 16 + cg + h * 8;
                    float ks = acc[i][jn][h * 2 + 0] + bk_;
                    float vs = acc[i][jn][h * 2 + 1] + bv_;
                    g_v16[(size_t)row * DIM + d] = f2h(vs);
                    sd_loc[jn] += ks * vs;
                    sk_loc[jn] += ks;
                    sk2 += ks * ks;
                }
            }
        }
        // reduce across cg (lanes differ in bits 2..4)
        #pragma unroll
        for (int jn = 0; jn < 8; jn++) {
            #pragma unroll
            for (int o = 4; o < 32; o <<= 1) {
                sd_loc[jn] += __shfl_xor_sync(0xffffffffu, sd_loc[jn], o);
                sk_loc[jn] += __shfl_xor_sync(0xffffffffu, sk_loc[jn], o);
            }
        }
        if (lane < 4) {
            #pragma unroll
            for (int jn = 0; jn < 8; jn++) {
                int dl = wn * 32 + jn * 4 + lane;
                atomicAdd(&sdS[dl], sd_loc[jn]);
                atomicAdd(&skS[dl], sk_loc[jn]);
            }
        }
        #pragma unroll
        for (int o = 16; o; o >>= 1) sk2 += __shfl_xor_sync(0xffffffffu, sk2, o);
        if (lane == 0) atomicAdd(&g_red[2 * DIM + 1], sk2);
        __syncthreads();
        if (tid < 64) {
            int d = (col0 >> 1) + tid;
            atomicAdd(&g_red[d], sdS[tid]);
            atomicAdd(&g_red[DIM + d], skS[tid]);
        }
    }
}

// ---------------- launcher ----------------
extern "C" void kernel_launch(void* const* d_in, const int* in_sizes, int n_in,
                              void* d_out_v, int out_size) {
    const float* q_in = (const float*)d_in[0];
    const float* s_in = (const float*)d_in[1];
    const float* Wq = (const float*)d_in[2];  const float* bq = (const float*)d_in[3];
    const float* Wk = (const float*)d_in[4];  const float* bk = (const float*)d_in[5];
    const float* Wv = (const float*)d_in[6];  const float* bv = (const float*)d_in[7];
    const float* Wh = (const float*)d_in[8];  const float* bh = (const float*)d_in[9];
    const float* lnkg = (const float*)d_in[10]; const float* lnkb = (const float*)d_in[11];
    const float* lnqg = (const float*)d_in[12]; const float* lnqb = (const float*)d_in[13];
    const float* ln2g = (const float*)d_in[14]; const float* ln2b = (const float*)d_in[15];
    const float* W1 = (const float*)d_in[16]; const float* b1 = (const float*)d_in[17];
    const float* W2 = (const float*)d_in[18]; const float* b2 = (const float*)d_in[19];
    float* out = (float*)d_out_v;

    cudaFuncSetAttribute(mma_gemm<4,0>, cudaFuncAttributeMaxDynamicSharedMemorySize, SMEM_DYN);
    cudaFuncSetAttribute(mma_gemm<5,1>, cudaFuncAttributeMaxDynamicSharedMemorySize, SMEM_DYN);
    cudaFuncSetAttribute(mma_gemm<1,0>, cudaFuncAttributeMaxDynamicSharedMemorySize, SMEM_DYN);
    cudaFuncSetAttribute(mma_gemm<2,1>, cudaFuncAttributeMaxDynamicSharedMemorySize, SMEM_DYN);
    cudaFuncSetAttribute(mma_gemm<3,2>, cudaFuncAttributeMaxDynamicSharedMemorySize, SMEM_DYN);

    dim3 blk(256);
    dim3 gQ(DIM / 128, NE / 128);        // (4, 512)
    dim3 gKV(1024 / 128, NE / 128);      // (8, 512)

    // Launch order arranged so launch #6 (ncu -s 5 -c 1) is a GEMM.
    wsplit_kernel<<<(512*512/4 + 255)/256, 256>>>(Wq, OFF_Q, 512*512/4);        // 1
    ln_kernel<0><<<NE, 128>>>(q_in, lnqg, lnqb);                                 // 2: ln_qry -> aq
    zero_red_kernel<<<(2 * DIM + 8 + 127) / 128, 128>>>();                       // 3
    wsplit_kv_kernel<<<(512*512/4 + 255)/256, 256>>>(Wk, Wv);                    // 4
    ln_kernel<1><<<NE, 128>>>(s_in, lnkg, lnkb);                                 // 5: ln_src -> as
    mma_gemm<4, 0><<<gQ, blk, SMEM_DYN>>>(OFF_Q, bq, nullptr, nullptr, nullptr, NE, DIM, DIM);   // 6: Q
    mma_gemm<5, 1><<<gKV, blk, SMEM_DYN>>>(OFF_KV, bk, bv, nullptr, nullptr, NE, 1024, DIM);     // 7: KV
    wsplit_kernel<<<(512*512/4 + 255)/256, 256>>>(Wh, OFF_H, 512*512/4);
    wsplit_kernel<<<(512*2048/4 + 255)/256, 256>>>(W1, OFF_1, 512*2048/4);
    wsplit_kernel<<<(2048*512/4 + 255)/256, 256>>>(W2, OFF_2, 2048*512/4);

    attn_kernel<<<NE, 128>>>();                    // -> g_aq (fp16 attn_output)

    // h_pre_ffn = source + attn @ Wh + bh -> out
    mma_gemm<1, 0><<<gQ, blk, SMEM_DYN>>>(OFF_H, bh, nullptr, s_in, out, NE, DIM, DIM);
    // y = LN(out) -> as
    ln_kernel<1><<<NE, 128>>>(out, ln2g, ln2b);
    // ffn = gelu(y @ W1 + b1) -> g_ff (fp16)
    mma_gemm<2, 1><<<dim3(DFF / 128, NE / 128), blk, SMEM_DYN>>>(OFF_1, b1, nullptr, nullptr, nullptr, NE, DFF, DIM);
    // out = out + ffn @ W2 + b2
    mma_gemm<3, 2><<<gQ, blk, SMEM_DYN>>>(OFF_2, b2, nullptr, out, out, NE, DIM, DFF);
}

// round 16
// speedup vs baseline: 6.6458x; 1.1564x over previous
#include <cuda_runtime.h>
#include <math.h>

#define NE   65536
#define DIM  512
#define DFF  2048
#define LN_EPS 1e-5f

typedef unsigned short u16;
typedef unsigned int   u32;

// ---------------- scratch (device globals; no allocations) ----------------
__device__ __align__(16) u16 g_q16[(size_t)NE * DIM];  // qs (fp16, from Q gemm epilogue)
__device__ __align__(16) u16 g_v16[(size_t)NE * DIM];  // vs (fp16, from KV gemm epilogue)
__device__ __align__(16) u16 g_aq[(size_t)NE * DIM];   // ln_qry, later attn_output
__device__ __align__(16) u16 g_as[(size_t)NE * DIM];   // ln_src, later y (ln2 out)
__device__ __align__(16) u16 g_ff[(size_t)NE * DFF];   // gelu output
// weights single fp16;  KV interleaved: col 2d = Wk[:,d], col 2d+1 = Wv[:,d]
#define OFF_Q 0
#define OFF_KV (512*512)
#define OFF_H (3*512*512)
#define OFF_1 (4*512*512)
#define OFF_2 (4*512*512 + 512*2048)
#define W_TOT (4*512*512 + 2*512*2048)
__device__ __align__(16) u16 g_w[W_TOT];
// [0,DIM)=diag_raw  [DIM,2DIM)=ksum_raw  [2DIM]=|qs|^2  [2DIM+1]=|ks|^2
__device__ __align__(16) float g_red[2 * DIM + 8];

// ---------------- fp16-as-bits helpers ----------------
__device__ __forceinline__ u16 f2h(float x) {
    u16 h;
    asm("cvt.rn.f16.f32 %0, %1;" : "=h"(h) : "f"(x));
    return h;
}
__device__ __forceinline__ float h2f(u16 h) {
    float f;
    asm("cvt.f32.f16 %0, %1;" : "=f"(f) : "h"(h));
    return f;
}
__device__ __forceinline__ u32 pack2(u16 a, u16 b) {
    return (u32)a | ((u32)b << 16);
}

__device__ __forceinline__ u32 smem_u32(const void* p) {
    return (u32)__cvta_generic_to_shared(p);
}
__device__ __forceinline__ void ldsm_x4(u32* r, u32 a) {
    asm volatile("ldmatrix.sync.aligned.m8n8.x4.shared.b16 {%0,%1,%2,%3}, [%4];"
                 : "=r"(r[0]), "=r"(r[1]), "=r"(r[2]), "=r"(r[3]) : "r"(a));
}
__device__ __forceinline__ void ldsm_x4t(u32* r, u32 a) {
    asm volatile("ldmatrix.sync.aligned.m8n8.x4.trans.shared.b16 {%0,%1,%2,%3}, [%4];"
                 : "=r"(r[0]), "=r"(r[1]), "=r"(r[2]), "=r"(r[3]) : "r"(a));
}
__device__ __forceinline__ void mma16816(float* d, const u32* a, const u32* b) {
    asm volatile("mma.sync.aligned.m16n8k16.row.col.f32.f16.f16.f32 "
                 "{%0,%1,%2,%3}, {%4,%5,%6,%7}, {%8,%9}, {%0,%1,%2,%3};"
                 : "+f"(d[0]), "+f"(d[1]), "+f"(d[2]), "+f"(d[3])
                 : "r"(a[0]), "r"(a[1]), "r"(a[2]), "r"(a[3]), "r"(b[0]), "r"(b[1]));
}
__device__ __forceinline__ void cpa16(u32 dst, const void* src) {
    asm volatile("cp.async.cg.shared.global [%0], [%1], 16;" :: "r"(dst), "l"(src));
}
__device__ __forceinline__ void cp_commit() {
    asm volatile("cp.async.commit_group;");
}
template <int N>
__device__ __forceinline__ void cp_wait() {
    asm volatile("cp.async.wait_group %0;" :: "n"(N));
}

// ---------------- small kernels ----------------
__global__ void zero_red_kernel() {
    int i = blockIdx.x * blockDim.x + threadIdx.x;
    if (i < 2 * DIM + 8) g_red[i] = 0.0f;
}

__global__ void wsplit_kernel(const float* __restrict__ src, int off, int n4) {
    int i = blockIdx.x * 256 + threadIdx.x;
    if (i < n4) {
        float4 v = ((const float4*)src)[i];
        size_t o = (size_t)off + (size_t)i * 4;
        *(u32*)(g_w + o)     = pack2(f2h(v.x), f2h(v.y));
        *(u32*)(g_w + o + 2) = pack2(f2h(v.z), f2h(v.w));
    }
}

// interleave Wk|Wv -> g_w[OFF_KV + k*1024 + 2d(+1)]
__global__ void wsplit_kv_kernel(const float* __restrict__ Wk, const float* __restrict__ Wv) {
    int i = blockIdx.x * 256 + threadIdx.x;   // over 512*512/4
    if (i < 512 * 512 / 4) {
        int k = i >> 7, dq = i & 127;         // d0 = dq*4
        float4 a = ((const float4*)(Wk + (size_t)k * 512))[dq];
        float4 b = ((const float4*)(Wv + (size_t)k * 512))[dq];
        size_t o = (size_t)OFF_KV + (size_t)k * 1024 + dq * 8;
        *(u32*)(g_w + o)     = pack2(f2h(a.x), f2h(b.x));
        *(u32*)(g_w + o + 2) = pack2(f2h(a.y), f2h(b.y));
        *(u32*)(g_w + o + 4) = pack2(f2h(a.z), f2h(b.z));
        *(u32*)(g_w + o + 6) = pack2(f2h(a.w), f2h(b.w));
    }
}

// layernorm -> single fp16.  DST: 0 -> g_aq, 1 -> g_as
template <int DST>
__global__ void ln_kernel(const float* __restrict__ x,
                          const float* __restrict__ gamma, const float* __restrict__ beta) {
    u16* y = (DST == 0) ? g_aq : g_as;
    int row = blockIdx.x;
    int t = threadIdx.x;
    const float4* xin = (const float4*)(x + (size_t)row * DIM);
    float4 v = xin[t];
    float s1 = v.x + v.y + v.z + v.w;
    float s2 = v.x*v.x + v.y*v.y + v.z*v.z + v.w*v.w;
    #pragma unroll
    for (int o = 16; o; o >>= 1) {
        s1 += __shfl_xor_sync(0xffffffffu, s1, o);
        s2 += __shfl_xor_sync(0xffffffffu, s2, o);
    }
    __shared__ float sh1[4], sh2[4];
    int w = t >> 5;
    if ((t & 31) == 0) { sh1[w] = s1; sh2[w] = s2; }
    __syncthreads();
    s1 = sh1[0] + sh1[1] + sh1[2] + sh1[3];
    s2 = sh2[0] + sh2[1] + sh2[2] + sh2[3];
    float mean = s1 * (1.0f / DIM);
    float var  = s2 * (1.0f / DIM) - mean * mean;
    float rstd = rsqrtf(var + LN_EPS);
    float4 gg = ((const float4*)gamma)[t];
    float4 bb = ((const float4*)beta)[t];
    float o0 = (v.x - mean) * rstd * gg.x + bb.x;
    float o1 = (v.y - mean) * rstd * gg.y + bb.y;
    float o2 = (v.z - mean) * rstd * gg.z + bb.z;
    float o3 = (v.w - mean) * rstd * gg.w + bb.w;
    size_t off = (size_t)row * DIM + t * 4;
    *(u32*)(y + off)     = pack2(f2h(o0), f2h(o1));
    *(u32*)(y + off + 2) = pack2(f2h(o2), f2h(o3));
}

// attention finalize: reads g_q16/g_v16 + g_red, writes fp16 attn_output to g_aq
__global__ void attn_kernel() {
    int row = blockIdx.x;
    int t = threadIdx.x;  // cols 4t..4t+3; head = t/16
    float rFq = rsqrtf(g_red[2 * DIM]);
    float rFk = rsqrtf(g_red[2 * DIM + 1]);
    const float nf = (float)NE;
    size_t base = (size_t)row * DIM;
    u32 qa = ((const u32*)(g_q16 + base))[2 * t];
    u32 qb = ((const u32*)(g_q16 + base))[2 * t + 1];
    u32 va = ((const u32*)(g_v16 + base))[2 * t];
    u32 vb = ((const u32*)(g_v16 + base))[2 * t + 1];
    float q0 = h2f((u16)(qa & 0xFFFF)), q1 = h2f((u16)(qa >> 16));
    float q2 = h2f((u16)(qb & 0xFFFF)), q3 = h2f((u16)(qb >> 16));
    float v0 = h2f((u16)(va & 0xFFFF)), v1 = h2f((u16)(va >> 16));
    float v2 = h2f((u16)(vb & 0xFFFF)), v3 = h2f((u16)(vb >> 16));
    float4 dg = ((const float4*)(g_red))[t];
    float4 km = ((const float4*)(g_red + DIM))[t];
    float p = (q0*km.x + q1*km.y + q2*km.z + q3*km.w) * (rFq * rFk);
    #pragma unroll
    for (int o = 8; o; o >>= 1) p += __shfl_xor_sync(0xffffffffu, p, o);
    float inv = 1.0f / (p + nf);
    float s = rFq * rFk;
    float o0 = (q0 * s * dg.x + v0 * nf) * inv;
    float o1 = (q1 * s * dg.y + v1 * nf) * inv;
    float o2 = (q2 * s * dg.z + v2 * nf) * inv;
    float o3 = (q3 * s * dg.w + v3 * nf) * inv;
    size_t off = base + t * 4;
    *(u32*)(g_aq + off)     = pack2(f2h(o0), f2h(o1));
    *(u32*)(g_aq + off + 2) = pack2(f2h(o2), f2h(o3));
}

// ---------------- single-fp16 tensor-core GEMM, 3-stage cp.async, 1 sync/slab ----------------
// ASEL: 0 -> g_aq, 1 -> g_as, 2 -> g_ff
// EPI 1: +bias+res -> Carg     EPI 2: gelu(+bias) -> g_ff(fp16)   EPI 3: +bias+res -> Carg
// EPI 4: Q  (+bias -> g_q16 fp16, accumulate |qs|^2)
// EPI 5: KV (interleaved cols; compute diag/ksum/|ks|^2, store vs fp16; nothing else written)
// Stage (bytes): A[128x32]@0 (8K), B[32x128]@8192 (8K).  16KB/stage.
// 2 CTAs/SM (regs ~100 < 128 cap): 4 warps/SMSP hides ldsm->mma latency + barriers.
#define STG_BYTES 16384
#define SMEM_DYN (3 * STG_BYTES)
template <int EPI, int ASEL>
__global__ void __launch_bounds__(256, 2)
mma_gemm(int boff, const float* __restrict__ bias, const float* __restrict__ bias2,
         const float* __restrict__ res, float* __restrict__ Carg, int M, int N, int K)
{
    const u16* A = (ASEL == 0) ? g_aq : (ASEL == 1) ? g_as : g_ff;
    const u16* B = g_w + boff;

    extern __shared__ __align__(16) u16 smem[];
    const int tid = threadIdx.x, lane = tid & 31, warp = tid >> 5;
    const int wm = warp >> 1, wn = warp & 1;            // 4 x 2 warp grid, 32x64
    const int row0 = blockIdx.y * 128;
    const int col0 = blockIdx.x * 128;

    float acc[2][8][4];
    #pragma unroll
    for (int i = 0; i < 2; i++)
        #pragma unroll
        for (int j = 0; j < 8; j++)
            #pragma unroll
            for (int c = 0; c < 4; c++) acc[i][j][c] = 0.0f;

    const u32 sBase = smem_u32(smem);

    const int lrA = lane & 15, lgA = lane >> 4;
    const int lkB = (lane & 7) + ((lane >> 3) & 1) * 8;
    const int lgB = lane >> 4;
    const int ar = tid >> 2, aq = tid & 3;
    const int br = tid >> 4, bq = tid & 15;

    u32 dA0 = (u32)((ar)      * 32 + 8 * (aq ^ (((ar)      >> 1) & 3))) * 2;
    u32 dA1 = (u32)((ar + 64) * 32 + 8 * (aq ^ (((ar + 64) >> 1) & 3))) * 2;
    u32 dB0 = (u32)((br)      * 128 + 8 * (bq ^ ((br)      & 7))) * 2 + 8192;
    u32 dB1 = (u32)((br + 16) * 128 + 8 * (bq ^ ((br + 16) & 7))) * 2 + 8192;

    const int nk = K >> 5;

    auto load_stage = [&](int stage, int slab) {
        int k0 = slab << 5;
        u32 sb = sBase + stage * STG_BYTES;
        const u16* a0 = A + (size_t)(row0 + ar) * K + k0 + aq * 8;
        const u16* a1 = A + (size_t)(row0 + ar + 64) * K + k0 + aq * 8;
        cpa16(sb + dA0, a0);
        cpa16(sb + dA1, a1);
        const u16* b0 = B + (size_t)(k0 + br) * N + col0 + bq * 8;
        const u16* b1 = B + (size_t)(k0 + br + 16) * N + col0 + bq * 8;
        cpa16(sb + dB0, b0);
        cpa16(sb + dB1, b1);
        cp_commit();
    };

    load_stage(0, 0);
    load_stage(1, 1);

    int stage = 0;
    for (int it = 0; it < nk; it++) {
        if (it + 1 < nk) cp_wait<1>(); else cp_wait<0>();
        __syncthreads();

        const u32 stA = sBase + stage * STG_BYTES;
        const u32 stB = stA + 8192;
        #pragma unroll
        for (int ks = 0; ks < 32; ks += 16) {
            u32 ahf[2][4];
            #pragma unroll
            for (int i = 0; i < 2; i++) {
                int r = wm * 32 + i * 16 + lrA;
                int G = (ks >> 3) + lgA;
                u32 off = (u32)(r * 32 + 8 * (G ^ ((r >> 1) & 3))) * 2;
                ldsm_x4(ahf[i], stA + off);
            }
            int kB = ks + lkB;
            int swb = kB & 7;
            #pragma unroll
            for (int jp = 0; jp < 4; jp++) {
                int G = wn * 8 + jp * 2 + lgB;
                u32 off = (u32)(kB * 128 + 8 * (G ^ swb)) * 2;
                u32 bhf[4];
                ldsm_x4t(bhf, stB + off);
                #pragma unroll
                for (int i = 0; i < 2; i++) {
                    #pragma unroll
                    for (int jj = 0; jj < 2; jj++) {
                        mma16816(acc[i][jp * 2 + jj], ahf[i], bhf + 2 * jj);
                    }
                }
            }
        }
        if (it + 2 < nk) {
            int ns = stage + 2;
            if (ns >= 3) ns -= 3;
            load_stage(ns, it + 2);
        }
        stage = (stage == 2) ? 0 : stage + 1;
    }

    const int cg = lane >> 2, ct = lane & 3;

    if (EPI <= 3) {
        // standard epilogues
        #pragma unroll
        for (int i = 0; i < 2; i++) {
            #pragma unroll
            for (int jn = 0; jn < 8; jn++) {
                int col = col0 + wn * 64 + jn * 8 + ct * 2;
                float b0 = bias[col], b1 = bias[col + 1];
                #pragma unroll
                for (int h = 0; h < 2; h++) {
                    int row = row0 + wm * 32 + i * 16 + cg + h * 8;
                    size_t idx = (size_t)row * N + col;
                    float v0 = acc[i][jn][h * 2 + 0] + b0;
                    float v1 = acc[i][jn][h * 2 + 1] + b1;
                    if (EPI == 1 || EPI == 3) {
                        float2 r2 = *(const float2*)(res + idx);
                        v0 += r2.x; v1 += r2.y;
                    }
                    if (EPI == 2) {
                        v0 = 0.5f * v0 * (1.0f + erff(v0 * 0.7071067811865476f));
                        v1 = 0.5f * v1 * (1.0f + erff(v1 * 0.7071067811865476f));
                        *(u32*)(g_ff + idx) = pack2(f2h(v0), f2h(v1));
                    } else {
                        *(float2*)(Carg + idx) = make_float2(v0, v1);
                    }
                }
            }
        }
    } else if (EPI == 4) {
        // Q: store fp16 + accumulate |qs|^2
        float sq2 = 0.0f;
        #pragma unroll
        for (int i = 0; i < 2; i++) {
            #pragma unroll
            for (int jn = 0; jn < 8; jn++) {
                int col = col0 + wn * 64 + jn * 8 + ct * 2;
                float b0 = bias[col], b1 = bias[col + 1];
                #pragma unroll
                for (int h = 0; h < 2; h++) {
                    int row = row0 + wm * 32 + i * 16 + cg + h * 8;
                    size_t idx = (size_t)row * N + col;
                    float v0 = acc[i][jn][h * 2 + 0] + b0;
                    float v1 = acc[i][jn][h * 2 + 1] + b1;
                    sq2 += v0 * v0 + v1 * v1;
                    *(u32*)(g_q16 + idx) = pack2(f2h(v0), f2h(v1));
                }
            }
        }
        #pragma unroll
        for (int o = 16; o; o >>= 1) sq2 += __shfl_xor_sync(0xffffffffu, sq2, o);
        if (lane == 0) atomicAdd(&g_red[2 * DIM], sq2);
    } else {
        // KV: interleaved cols (even=ks, odd=vs). diag/ksum/|ks|^2 + store vs fp16.
        float* sdS = (float*)smem;          // [64]
        float* skS = sdS + 64;              // [64]
        __syncthreads();
        if (tid < 64) { sdS[tid] = 0.0f; skS[tid] = 0.0f; }
        __syncthreads();

        float sd_loc[8], sk_loc[8], sk2 = 0.0f;
        #pragma unroll
        for (int jn = 0; jn < 8; jn++) { sd_loc[jn] = 0.0f; sk_loc[jn] = 0.0f; }
        #pragma unroll
        for (int i = 0; i < 2; i++) {
            #pragma unroll
            for (int jn = 0; jn < 8; jn++) {
                int col = col0 + wn * 64 + jn * 8 + ct * 2;   // even
                int d = col >> 1;
                float bk_ = bias[d], bv_ = bias2[d];
                #pragma unroll
                for (int h = 0; h < 2; h++) {
                    int row = row0 + wm * 32 + i * 16 + cg + h * 8;
                    float ks = acc[i][jn][h * 2 + 0] + bk_;
                    float vs = acc[i][jn][h * 2 + 1] + bv_;
                    g_v16[(size_t)row * DIM + d] = f2h(vs);
                    sd_loc[jn] += ks * vs;
                    sk_loc[jn] += ks;
                    sk2 += ks * ks;
                }
            }
        }
        // reduce across cg (lanes differ in bits 2..4)
        #pragma unroll
        for (int jn = 0; jn < 8; jn++) {
            #pragma unroll
            for (int o = 4; o < 32; o <<= 1) {
                sd_loc[jn] += __shfl_xor_sync(0xffffffffu, sd_loc[jn], o);
                sk_loc[jn] += __shfl_xor_sync(0xffffffffu, sk_loc[jn], o);
            }
        }
        if (lane < 4) {
            #pragma unroll
            for (int jn = 0; jn < 8; jn++) {
                int dl = wn * 32 + jn * 4 + lane;
                atomicAdd(&sdS[dl], sd_loc[jn]);
                atomicAdd(&skS[dl], sk_loc[jn]);
            }
        }
        #pragma unroll
        for (int o = 16; o; o >>= 1) sk2 += __shfl_xor_sync(0xffffffffu, sk2, o);
        if (lane == 0) atomicAdd(&g_red[2 * DIM + 1], sk2);
        __syncthreads();
        if (tid < 64) {
            int d = (col0 >> 1) + tid;
            atomicAdd(&g_red[d], sdS[tid]);
            atomicAdd(&g_red[DIM + d], skS[tid]);
        }
    }
}

// ---------------- launcher ----------------
extern "C" void kernel_launch(void* const* d_in, const int* in_sizes, int n_in,
                              void* d_out_v, int out_size) {
    const float* q_in = (const float*)d_in[0];
    const float* s_in = (const float*)d_in[1];
    const float* Wq = (const float*)d_in[2];  const float* bq = (const float*)d_in[3];
    const float* Wk = (const float*)d_in[4];  const float* bk = (const float*)d_in[5];
    const float* Wv = (const float*)d_in[6];  const float* bv = (const float*)d_in[7];
    const float* Wh = (const float*)d_in[8];  const float* bh = (const float*)d_in[9];
    const float* lnkg = (const float*)d_in[10]; const float* lnkb = (const float*)d_in[11];
    const float* lnqg = (const float*)d_in[12]; const float* lnqb = (const float*)d_in[13];
    const float* ln2g = (const float*)d_in[14]; const float* ln2b = (const float*)d_in[15];
    const float* W1 = (const float*)d_in[16]; const float* b1 = (const float*)d_in[17];
    const float* W2 = (const float*)d_in[18]; const float* b2 = (const float*)d_in[19];
    float* out = (float*)d_out_v;

    cudaFuncSetAttribute(mma_gemm<4,0>, cudaFuncAttributeMaxDynamicSharedMemorySize, SMEM_DYN);
    cudaFuncSetAttribute(mma_gemm<5,1>, cudaFuncAttributeMaxDynamicSharedMemorySize, SMEM_DYN);
    cudaFuncSetAttribute(mma_gemm<1,0>, cudaFuncAttributeMaxDynamicSharedMemorySize, SMEM_DYN);
    cudaFuncSetAttribute(mma_gemm<2,1>, cudaFuncAttributeMaxDynamicSharedMemorySize, SMEM_DYN);
    cudaFuncSetAttribute(mma_gemm<3,2>, cudaFuncAttributeMaxDynamicSharedMemorySize, SMEM_DYN);

    dim3 blk(256);
    dim3 gQ(DIM / 128, NE / 128);        // (4, 512)
    dim3 gKV(1024 / 128, NE / 128);      // (8, 512)

    // Launch order arranged so launch #6 (ncu -s 5 -c 1) is a GEMM.
    wsplit_kernel<<<(512*512/4 + 255)/256, 256>>>(Wq, OFF_Q, 512*512/4);        // 1
    ln_kernel<0><<<NE, 128>>>(q_in, lnqg, lnqb);                                 // 2: ln_qry -> aq
    zero_red_kernel<<<(2 * DIM + 8 + 127) / 128, 128>>>();                       // 3
    wsplit_kv_kernel<<<(512*512/4 + 255)/256, 256>>>(Wk, Wv);                    // 4
    ln_kernel<1><<<NE, 128>>>(s_in, lnkg, lnkb);                                 // 5: ln_src -> as
    mma_gemm<4, 0><<<gQ, blk, SMEM_DYN>>>(OFF_Q, bq, nullptr, nullptr, nullptr, NE, DIM, DIM);   // 6: Q
    mma_gemm<5, 1><<<gKV, blk, SMEM_DYN>>>(OFF_KV, bk, bv, nullptr, nullptr, NE, 1024, DIM);     // 7: KV
    wsplit_kernel<<<(512*512/4 + 255)/256, 256>>>(Wh, OFF_H, 512*512/4);
    wsplit_kernel<<<(512*2048/4 + 255)/256, 256>>>(W1, OFF_1, 512*2048/4);
    wsplit_kernel<<<(2048*512/4 + 255)/256, 256>>>(W2, OFF_2, 2048*512/4);

    attn_kernel<<<NE, 128>>>();                    // -> g_aq (fp16 attn_output)

    // h_pre_ffn = source + attn @ Wh + bh -> out
    mma_gemm<1, 0><<<gQ, blk, SMEM_DYN>>>(OFF_H, bh, nullptr, s_in, out, NE, DIM, DIM);
    // y = LN(out) -> as
    ln_kernel<1><<<NE, 128>>>(out, ln2g, ln2b);
    // ffn = gelu(y @ W1 + b1) -> g_ff (fp16)
    mma_gemm<2, 1><<<dim3(DFF / 128, NE / 128), blk, SMEM_DYN>>>(OFF_1, b1, nullptr, nullptr, nullptr, NE, DFF, DIM);
    // out = out + ffn @ W2 + b2
    mma_gemm<3, 2><<<gQ, blk, SMEM_DYN>>>(OFF_2, b2, nullptr, out, out, NE, DIM, DFF);
}